// round 1
// baseline (speedup 1.0000x reference)
#include <cuda_runtime.h>

// Problem constants (fixed by dataset)
#define BATCH 4
#define T_SEQ 1024
#define D_MOD 2048
#define NHEAD 32
#define HDIM  64
#define M_ROWS (BATCH * T_SEQ)   // 4096

// Scratch (device globals; allocation-free per harness rules)
__device__ float g_q[(long long)BATCH * T_SEQ * D_MOD];
__device__ float g_ctx[(long long)BATCH * T_SEQ * D_MOD];

// ---------------------------------------------------------------------------
// SGEMM: C[row -> remapped] = A(MxK) @ W(KxN) + bias
// BM=128, BN=128, BK=16, 256 threads, 8x8 per thread, double-buffered smem.
// Output row r=(b*T+t) is written at: C[b*outerStride + outOffset + t*N + col]
// ---------------------------------------------------------------------------
__global__ __launch_bounds__(256, 2)
void sgemm_bias_kernel(const float* __restrict__ A, const float* __restrict__ W,
                       const float* __restrict__ bias, float* __restrict__ C,
                       int K, int N, long long outerStride, long long outOffset)
{
    __shared__ float As[2][16][128];
    __shared__ float Ws[2][16][128];

    const int tid = threadIdx.x;
    const int tm = tid >> 4;       // 0..15
    const int tn = tid & 15;       // 0..15
    const int bm = blockIdx.y;
    const int bn = blockIdx.x;

    const float* Ablk = A + (long long)bm * 128 * K;
    const float* Wblk = W + (long long)bn * 128;

    // A loader: 512 float4 over 128 rows x 16 cols; thread handles 2 (rows r, r+64)
    const int arow = tid >> 2;
    const int ac4  = (tid & 3) * 4;
    // W loader: 512 float4 over 16 rows x 128 cols; thread handles 2 (rows r, r+8)
    const int wrow = tid >> 5;
    const int wc   = (tid & 31) * 4;

    float4 pa0, pa1, pw0, pw1;

    // prefetch kb=0
    pa0 = *(const float4*)(Ablk + (long long)arow * K + ac4);
    pa1 = *(const float4*)(Ablk + (long long)(arow + 64) * K + ac4);
    pw0 = *(const float4*)(Wblk + (long long)wrow * N + wc);
    pw1 = *(const float4*)(Wblk + (long long)(wrow + 8) * N + wc);

    As[0][ac4 + 0][arow] = pa0.x; As[0][ac4 + 1][arow] = pa0.y;
    As[0][ac4 + 2][arow] = pa0.z; As[0][ac4 + 3][arow] = pa0.w;
    As[0][ac4 + 0][arow + 64] = pa1.x; As[0][ac4 + 1][arow + 64] = pa1.y;
    As[0][ac4 + 2][arow + 64] = pa1.z; As[0][ac4 + 3][arow + 64] = pa1.w;
    *(float4*)&Ws[0][wrow][wc]     = pw0;
    *(float4*)&Ws[0][wrow + 8][wc] = pw1;
    __syncthreads();

    float acc[8][8];
    #pragma unroll
    for (int i = 0; i < 8; i++)
        #pragma unroll
        for (int j = 0; j < 8; j++) acc[i][j] = 0.0f;

    const int NK = K >> 4;
    for (int kb = 0; kb < NK; kb++) {
        const int buf = kb & 1;
        if (kb + 1 < NK) {
            const float* An = Ablk + (kb + 1) * 16;
            pa0 = *(const float4*)(An + (long long)arow * K + ac4);
            pa1 = *(const float4*)(An + (long long)(arow + 64) * K + ac4);
            const float* Wn = Wblk + (long long)(kb + 1) * 16 * N;
            pw0 = *(const float4*)(Wn + (long long)wrow * N + wc);
            pw1 = *(const float4*)(Wn + (long long)(wrow + 8) * N + wc);
        }
        #pragma unroll
        for (int kk = 0; kk < 16; kk++) {
            float a[8], b[8];
            *(float4*)(a)     = *(const float4*)&As[buf][kk][tm * 8];
            *(float4*)(a + 4) = *(const float4*)&As[buf][kk][tm * 8 + 4];
            *(float4*)(b)     = *(const float4*)&Ws[buf][kk][tn * 8];
            *(float4*)(b + 4) = *(const float4*)&Ws[buf][kk][tn * 8 + 4];
            #pragma unroll
            for (int i = 0; i < 8; i++)
                #pragma unroll
                for (int j = 0; j < 8; j++)
                    acc[i][j] += a[i] * b[j];
        }
        if (kb + 1 < NK) {
            const int nb = buf ^ 1;
            As[nb][ac4 + 0][arow] = pa0.x; As[nb][ac4 + 1][arow] = pa0.y;
            As[nb][ac4 + 2][arow] = pa0.z; As[nb][ac4 + 3][arow] = pa0.w;
            As[nb][ac4 + 0][arow + 64] = pa1.x; As[nb][ac4 + 1][arow + 64] = pa1.y;
            As[nb][ac4 + 2][arow + 64] = pa1.z; As[nb][ac4 + 3][arow + 64] = pa1.w;
            *(float4*)&Ws[nb][wrow][wc]     = pw0;
            *(float4*)&Ws[nb][wrow + 8][wc] = pw1;
        }
        __syncthreads();
    }

    // epilogue with bias + per-batch row remap
    #pragma unroll
    for (int i = 0; i < 8; i++) {
        const int row = bm * 128 + tm * 8 + i;
        const int bb = row >> 10;        // T_SEQ = 1024
        const int t  = row & 1023;
        const long long base = (long long)bb * outerStride + outOffset + (long long)t * N;
        #pragma unroll
        for (int j = 0; j < 8; j++) {
            const int col = bn * 128 + tn * 8 + j;
            C[base + col] = acc[i][j] + bias[col];
        }
    }
}

// ---------------------------------------------------------------------------
// Flash attention (fp32, causal). Block = 64 queries of one (b,h).
// 256 threads as 16x16; each thread owns a 4(q)x4(k) S-tile and 4(q)x4(hd) O-tile.
// Smem: Qs[64][65], Ks[64][65] (aliased as P^T after S), Vs[64][64].
// ---------------------------------------------------------------------------
__global__ __launch_bounds__(256)
void attn_kernel(const float* __restrict__ qbuf, const float* __restrict__ cache,
                 float* __restrict__ ctx)
{
    extern __shared__ float sm[];
    float* Qs = sm;                 // [64][65]
    float* Ks = sm + 64 * 65;       // [64][65] (also P^T buffer)
    float* Vs = sm + 2 * 64 * 65;   // [64][64]

    const int qt = blockIdx.x;      // 0..15
    const int h  = blockIdx.y;      // 0..31
    const int b  = blockIdx.z;      // 0..3
    const int tid = threadIdx.x;
    const int tx = tid & 15;        // key / hd dimension
    const int ty = tid >> 4;        // query dimension

    const float scale = 0.125f;     // HD^-0.5

    // load Q tile (scaled)
    const float* qbase = qbuf + ((long long)(b * T_SEQ + qt * 64)) * D_MOD + h * HDIM;
    for (int idx = tid; idx < 64 * 64; idx += 256) {
        const int r = idx >> 6, c = idx & 63;
        Qs[r * 65 + c] = qbase[(long long)r * D_MOD + c] * scale;
    }

    float m_old[4], lsum[4], o[4][4];
    #pragma unroll
    for (int i = 0; i < 4; i++) {
        m_old[i] = -1e30f;
        lsum[i] = 0.0f;
        #pragma unroll
        for (int j = 0; j < 4; j++) o[i][j] = 0.0f;
    }

    const float* kbase = cache + ((long long)(b * 2 + 0) * T_SEQ) * D_MOD + h * HDIM;
    const float* vbase = cache + ((long long)(b * 2 + 1) * T_SEQ) * D_MOD + h * HDIM;

    for (int kt = 0; kt <= qt; kt++) {
        __syncthreads();   // prior P^T/V reads done (and Q-load on first iter)
        for (int idx = tid; idx < 64 * 64; idx += 256) {
            const int r = idx >> 6, c = idx & 63;
            Ks[r * 65 + c] = kbase[(long long)(kt * 64 + r) * D_MOD + c];
            Vs[r * 64 + c] = vbase[(long long)(kt * 64 + r) * D_MOD + c];
        }
        __syncthreads();

        // S = Qs @ Ks^T  (4x4 per thread)
        float s4[4][4];
        #pragma unroll
        for (int i = 0; i < 4; i++)
            #pragma unroll
            for (int j = 0; j < 4; j++) s4[i][j] = 0.0f;

        #pragma unroll 4
        for (int kk = 0; kk < 64; kk++) {
            float qv[4], kv[4];
            #pragma unroll
            for (int i = 0; i < 4; i++) qv[i] = Qs[(ty * 4 + i) * 65 + kk];
            #pragma unroll
            for (int j = 0; j < 4; j++) kv[j] = Ks[(tx * 4 + j) * 65 + kk];
            #pragma unroll
            for (int i = 0; i < 4; i++)
                #pragma unroll
                for (int j = 0; j < 4; j++)
                    s4[i][j] += qv[i] * kv[j];
        }

        // causal mask on the diagonal tile
        if (kt == qt) {
            #pragma unroll
            for (int i = 0; i < 4; i++)
                #pragma unroll
                for (int j = 0; j < 4; j++)
                    if (tx * 4 + j > ty * 4 + i) s4[i][j] = -1e30f;
        }

        // online softmax stats (reduce across the 16 lanes sharing each q-row)
        float mnew[4], alpha[4], rs[4];
        float p4[4][4];
        #pragma unroll
        for (int i = 0; i < 4; i++) {
            float mt = s4[i][0];
            #pragma unroll
            for (int j = 1; j < 4; j++) mt = fmaxf(mt, s4[i][j]);
            #pragma unroll
            for (int off = 8; off; off >>= 1)
                mt = fmaxf(mt, __shfl_xor_sync(0xffffffffu, mt, off));
            mnew[i] = fmaxf(m_old[i], mt);
            alpha[i] = __expf(m_old[i] - mnew[i]);
            float r = 0.0f;
            #pragma unroll
            for (int j = 0; j < 4; j++) {
                p4[i][j] = __expf(s4[i][j] - mnew[i]);
                r += p4[i][j];
            }
            #pragma unroll
            for (int off = 8; off; off >>= 1)
                r += __shfl_xor_sync(0xffffffffu, r, off);
            rs[i] = r;
            lsum[i] = lsum[i] * alpha[i] + rs[i];
            m_old[i] = mnew[i];
            #pragma unroll
            for (int j = 0; j < 4; j++) o[i][j] *= alpha[i];
        }

        __syncthreads();   // all S reads of Ks finished before alias as P^T
        // write P^T: Pt[k][q]
        #pragma unroll
        for (int i = 0; i < 4; i++)
            #pragma unroll
            for (int j = 0; j < 4; j++)
                Ks[(tx * 4 + j) * 65 + ty * 4 + i] = p4[i][j];
        __syncthreads();

        // O += P @ V : o[i][j] += sum_kk Pt[kk][q0+i] * Vs[kk][hd0+j]
        #pragma unroll 4
        for (int kk = 0; kk < 64; kk++) {
            float pv[4], vv[4];
            #pragma unroll
            for (int i = 0; i < 4; i++) pv[i] = Ks[kk * 65 + ty * 4 + i];
            #pragma unroll
            for (int j = 0; j < 4; j++) vv[j] = Vs[kk * 64 + tx * 4 + j];
            #pragma unroll
            for (int i = 0; i < 4; i++)
                #pragma unroll
                for (int j = 0; j < 4; j++)
                    o[i][j] += pv[i] * vv[j];
        }
    }

    // write merged ctx: (b, t, h*64+hd)
    #pragma unroll
    for (int i = 0; i < 4; i++) {
        const long long row = (long long)(b * T_SEQ + qt * 64 + ty * 4 + i);
        float* obase = ctx + row * D_MOD + h * HDIM + tx * 4;
        const float inv_l = 1.0f / lsum[i];
        #pragma unroll
        for (int j = 0; j < 4; j++)
            obase[j] = o[i][j] * inv_l;
    }
}

// ---------------------------------------------------------------------------
// Launch
// ---------------------------------------------------------------------------
extern "C" void kernel_launch(void* const* d_in, const int* in_sizes, int n_in,
                              void* d_out, int out_size)
{
    const float* x  = (const float*)d_in[0];
    // d_in[1] attention_mask: exact causal additive mask — handled analytically
    // d_in[2] cache (zeros), d_in[3] cache_update_index (0): full overwrite
    const float* Wq = (const float*)d_in[4];
    const float* bq = (const float*)d_in[5];
    const float* Wk = (const float*)d_in[6];
    const float* bk = (const float*)d_in[7];
    const float* Wv = (const float*)d_in[8];
    const float* bv = (const float*)d_in[9];
    const float* Wo = (const float*)d_in[10];
    const float* bo = (const float*)d_in[11];

    float* out = (float*)d_out;
    float* cache_out = out + (long long)BATCH * T_SEQ * D_MOD;  // new_cache region

    float* qbuf = nullptr;
    float* ctxbuf = nullptr;
    cudaGetSymbolAddress((void**)&qbuf, g_q);
    cudaGetSymbolAddress((void**)&ctxbuf, g_ctx);

    const int smem_attn = (64 * 65 + 64 * 65 + 64 * 64) * sizeof(float);  // 49664
    cudaFuncSetAttribute(attn_kernel, cudaFuncAttributeMaxDynamicSharedMemorySize, smem_attn);

    const long long TN  = (long long)T_SEQ * D_MOD;   // per-batch plain stride
    dim3 ggrid(D_MOD / 128, M_ROWS / 128);            // (16, 32)

    // Q projection -> scratch
    sgemm_bias_kernel<<<ggrid, 256>>>(x, Wq, bq, qbuf, D_MOD, D_MOD, TN, 0);
    // K projection -> cache[:,0] region of d_out
    sgemm_bias_kernel<<<ggrid, 256>>>(x, Wk, bk, cache_out, D_MOD, D_MOD, 2 * TN, 0);
    // V projection -> cache[:,1] region of d_out
    sgemm_bias_kernel<<<ggrid, 256>>>(x, Wv, bv, cache_out, D_MOD, D_MOD, 2 * TN, TN);

    // causal flash attention
    dim3 agrid(T_SEQ / 64, NHEAD, BATCH);             // (16, 32, 4)
    attn_kernel<<<agrid, 256, smem_attn>>>(qbuf, cache_out, ctxbuf);

    // output projection -> out
    sgemm_bias_kernel<<<ggrid, 256>>>(ctxbuf, Wo, bo, out, D_MOD, D_MOD, TN, 0);
}

// round 3
// speedup vs baseline: 3.5641x; 3.5641x over previous
#include <cuda_runtime.h>
#include <cuda_fp16.h>
#include <cstdint>

// Problem constants
#define BATCH 4
#define T_SEQ 1024
#define D_MOD 2048
#define NHEAD 32
#define HDIM  64
#define M_ROWS (BATCH * T_SEQ)      // 4096

#define STAGES 4
#define BK 64                       // fp16 K-slab (128 bytes per row)
#define NSLAB (D_MOD / BK)          // 32
#define STAGE_BYTES 32768           // (128*64 + 128*64) * 2

// Scratch (device globals; allocation-free per harness rules)
__device__ __half g_xh[(size_t)M_ROWS * D_MOD];          // x in fp16 [M][K]
__device__ __half g_wh[4ull * D_MOD * D_MOD];            // weights fp16 [N][K] x4
__device__ __half g_ctxh[(size_t)M_ROWS * D_MOD];        // attn output fp16 [M][K]
__device__ float  g_q[(size_t)M_ROWS * D_MOD];           // Q projection f32

// ---------------------------------------------------------------------------
// helpers
// ---------------------------------------------------------------------------
__device__ __forceinline__ uint32_t smem_u32(const void* p) {
    return (uint32_t)__cvta_generic_to_shared(p);
}
#define SWZ(o) ((o) ^ (((o) >> 3) & 0x70))

__device__ __forceinline__ void cp16(uint32_t dst, const void* src) {
    asm volatile("cp.async.cg.shared.global [%0], [%1], 16;" :: "r"(dst), "l"(src));
}

__device__ __forceinline__ void ldmx4(uint32_t* r, uint32_t addr) {
    asm volatile("ldmatrix.sync.aligned.m8n8.x4.shared.b16 {%0,%1,%2,%3}, [%4];"
                 : "=r"(r[0]), "=r"(r[1]), "=r"(r[2]), "=r"(r[3]) : "r"(addr));
}

__device__ __forceinline__ void mma16816(float* c, const uint32_t* a,
                                         uint32_t b0, uint32_t b1) {
    asm volatile(
        "mma.sync.aligned.m16n8k16.row.col.f32.f16.f16.f32 "
        "{%0,%1,%2,%3}, {%4,%5,%6,%7}, {%8,%9}, {%0,%1,%2,%3};"
        : "+f"(c[0]), "+f"(c[1]), "+f"(c[2]), "+f"(c[3])
        : "r"(a[0]), "r"(a[1]), "r"(a[2]), "r"(a[3]), "r"(b0), "r"(b1));
}

// ---------------------------------------------------------------------------
// Prep: x (f32 [M][K]) -> fp16
// ---------------------------------------------------------------------------
__global__ __launch_bounds__(256)
void convert_x_kernel(const float* __restrict__ x, __half* __restrict__ xh)
{
    const size_t i = (size_t)blockIdx.x * 256 + threadIdx.x;   // float4 index
    float4 v = ((const float4*)x)[i];
    __half2* o = (__half2*)xh;
    o[i * 2 + 0] = __floats2half2_rn(v.x, v.y);
    o[i * 2 + 1] = __floats2half2_rn(v.z, v.w);
}

// ---------------------------------------------------------------------------
// Prep: W [K][N] f32 -> Wh [N][K] fp16 (transpose + convert), 4 matrices
// ---------------------------------------------------------------------------
__global__ __launch_bounds__(256)
void convert_wt_kernel(const float* __restrict__ w0, const float* __restrict__ w1,
                       const float* __restrict__ w2, const float* __restrict__ w3,
                       __half* __restrict__ dst)
{
    __shared__ float tile[32][33];
    const float* src = blockIdx.z == 0 ? w0 : blockIdx.z == 1 ? w1
                     : blockIdx.z == 2 ? w2 : w3;
    __half* d = dst + (size_t)blockIdx.z * D_MOD * D_MOD;
    const int tx = threadIdx.x & 31, ty = threadIdx.x >> 5;   // 32 x 8
    const int n0 = blockIdx.x * 32, k0 = blockIdx.y * 32;
    #pragma unroll
    for (int r = 0; r < 32; r += 8)
        tile[ty + r][tx] = src[(size_t)(k0 + ty + r) * D_MOD + n0 + tx];
    __syncthreads();
    #pragma unroll
    for (int r = 0; r < 32; r += 8)
        d[(size_t)(n0 + ty + r) * D_MOD + k0 + tx] = __float2half(tile[tx][ty + r]);
}

// ---------------------------------------------------------------------------
// fp16 tensor-core GEMM: C(f32) = A[M,K]h @ B[N,K]h^T + bias, per-batch row remap.
// CTA 128x128, BK=64, 4-stage cp.async, 8 warps (2M x 4N), warp tile 64x32.
// Output row m=(b*T+t) -> C[b*outerStride + outOffset + t*2048 + n].
// ---------------------------------------------------------------------------
__global__ __launch_bounds__(256, 1)
void gemm_hmma_kernel(const __half* __restrict__ A, const __half* __restrict__ B,
                      const float* __restrict__ bias, float* __restrict__ C,
                      long long outerStride, long long outOffset)
{
    extern __shared__ char dsmem_raw[];
    __shared__ float bias_s[128];

    const int tid  = threadIdx.x;
    const int lane = tid & 31;
    const int wid  = tid >> 5;
    const int wm   = wid & 1;          // 0..1
    const int wn   = wid >> 1;         // 0..3
    const int bm = blockIdx.y, bn = blockIdx.x;

    uint32_t sbase = smem_u32(dsmem_raw);
    sbase = (sbase + 1023u) & ~1023u;

    if (tid < 128) bias_s[tid] = bias[bn * 128 + tid];

    const __half* Ab = A + (size_t)bm * 128 * D_MOD;
    const __half* Bb = B + (size_t)bn * 128 * D_MOD;

    // prologue: load slabs 0..STAGES-2
    #pragma unroll
    for (int s = 0; s < STAGES - 1; s++) {
        const uint32_t stA = sbase + s * STAGE_BYTES;
        const uint32_t stB = stA + 16384u;
        const int kb = s * BK;
        #pragma unroll
        for (int t = 0; t < 4; t++) {
            const int c = tid + t * 256;
            const int r = c >> 3, u = c & 7;
            cp16(stA + SWZ((uint32_t)(r * 128 + u * 16)), Ab + (size_t)r * D_MOD + kb + u * 8);
            cp16(stB + SWZ((uint32_t)(r * 128 + u * 16)), Bb + (size_t)r * D_MOD + kb + u * 8);
        }
        asm volatile("cp.async.commit_group;" ::: "memory");
    }

    float acc[4][4][4];
    #pragma unroll
    for (int i = 0; i < 4; i++)
        #pragma unroll
        for (int j = 0; j < 4; j++)
            #pragma unroll
            for (int q = 0; q < 4; q++) acc[i][j][q] = 0.0f;

    // ldmatrix lane addressing components
    const int lrow = lane & 15;
    const int lcol = (lane >> 4) * 16;

    for (int i = 0; i < NSLAB; i++) {
        asm volatile("cp.async.wait_group %0;" :: "n"(STAGES - 2) : "memory");
        __syncthreads();

        // issue next load
        if (i + STAGES - 1 < NSLAB) {
            const int s = (i + STAGES - 1) & (STAGES - 1);
            const uint32_t stA = sbase + s * STAGE_BYTES;
            const uint32_t stB = stA + 16384u;
            const int kb = (i + STAGES - 1) * BK;
            #pragma unroll
            for (int t = 0; t < 4; t++) {
                const int c = tid + t * 256;
                const int r = c >> 3, u = c & 7;
                cp16(stA + SWZ((uint32_t)(r * 128 + u * 16)), Ab + (size_t)r * D_MOD + kb + u * 8);
                cp16(stB + SWZ((uint32_t)(r * 128 + u * 16)), Bb + (size_t)r * D_MOD + kb + u * 8);
            }
        }
        asm volatile("cp.async.commit_group;" ::: "memory");

        // compute slab i
        const int s = i & (STAGES - 1);
        const uint32_t stA = sbase + s * STAGE_BYTES;
        const uint32_t stB = stA + 16384u;

        #pragma unroll
        for (int ks = 0; ks < BK / 16; ks++) {
            uint32_t afr[4][4], bfr[2][4];
            #pragma unroll
            for (int mt = 0; mt < 4; mt++)
                ldmx4(afr[mt], stA + SWZ((uint32_t)((wm * 64 + mt * 16 + lrow) * 128
                                                    + ks * 32 + lcol)));
            #pragma unroll
            for (int bt = 0; bt < 2; bt++)
                ldmx4(bfr[bt], stB + SWZ((uint32_t)((wn * 32 + bt * 16 + lrow) * 128
                                                    + ks * 32 + lcol)));
            #pragma unroll
            for (int mt = 0; mt < 4; mt++)
                #pragma unroll
                for (int nt = 0; nt < 4; nt++) {
                    const int bt = nt >> 1, sub = nt & 1;
                    mma16816(acc[mt][nt], afr[mt], bfr[bt][sub], bfr[bt][sub + 2]);
                }
        }
        __syncthreads();
    }

    // epilogue: bias + per-batch row remap, float2 stores
    const int g = lane >> 2, t2 = (lane & 3) * 2;
    #pragma unroll
    for (int mt = 0; mt < 4; mt++) {
        #pragma unroll
        for (int half_m = 0; half_m < 2; half_m++) {
            const int row_g = bm * 128 + wm * 64 + mt * 16 + half_m * 8 + g;
            const int bb = row_g >> 10;
            const int tt = row_g & 1023;
            float* Crow = C + (long long)bb * outerStride + outOffset
                            + (long long)tt * D_MOD + bn * 128;
            #pragma unroll
            for (int nt = 0; nt < 4; nt++) {
                const int col = wn * 32 + nt * 8 + t2;
                float2 v;
                v.x = acc[mt][nt][half_m * 2 + 0] + bias_s[col];
                v.y = acc[mt][nt][half_m * 2 + 1] + bias_s[col + 1];
                *(float2*)(Crow + col) = v;
            }
        }
    }
}

// ---------------------------------------------------------------------------
// Flash attention (fp32, causal). Writes fp16 ctx for the output projection.
// ---------------------------------------------------------------------------
__global__ __launch_bounds__(256)
void attn_kernel(const float* __restrict__ qbuf, const float* __restrict__ cache,
                 __half* __restrict__ ctxh)
{
    extern __shared__ float sm[];
    float* Qs = sm;                 // [64][65]
    float* Ks = sm + 64 * 65;       // [64][65] (also P^T buffer)
    float* Vs = sm + 2 * 64 * 65;   // [64][64]

    const int qt = blockIdx.x;
    const int h  = blockIdx.y;
    const int b  = blockIdx.z;
    const int tid = threadIdx.x;
    const int tx = tid & 15;
    const int ty = tid >> 4;

    const float scale = 0.125f;

    const float* qbase = qbuf + ((long long)(b * T_SEQ + qt * 64)) * D_MOD + h * HDIM;
    for (int idx = tid; idx < 64 * 64; idx += 256) {
        const int r = idx >> 6, c = idx & 63;
        Qs[r * 65 + c] = qbase[(long long)r * D_MOD + c] * scale;
    }

    float m_old[4], lsum[4], o[4][4];
    #pragma unroll
    for (int i = 0; i < 4; i++) {
        m_old[i] = -1e30f;
        lsum[i] = 0.0f;
        #pragma unroll
        for (int j = 0; j < 4; j++) o[i][j] = 0.0f;
    }

    const float* kbase = cache + ((long long)(b * 2 + 0) * T_SEQ) * D_MOD + h * HDIM;
    const float* vbase = cache + ((long long)(b * 2 + 1) * T_SEQ) * D_MOD + h * HDIM;

    for (int kt = 0; kt <= qt; kt++) {
        __syncthreads();
        for (int idx = tid; idx < 64 * 64; idx += 256) {
            const int r = idx >> 6, c = idx & 63;
            Ks[r * 65 + c] = kbase[(long long)(kt * 64 + r) * D_MOD + c];
            Vs[r * 64 + c] = vbase[(long long)(kt * 64 + r) * D_MOD + c];
        }
        __syncthreads();

        float s4[4][4];
        #pragma unroll
        for (int i = 0; i < 4; i++)
            #pragma unroll
            for (int j = 0; j < 4; j++) s4[i][j] = 0.0f;

        #pragma unroll 4
        for (int kk = 0; kk < 64; kk++) {
            float qv[4], kv[4];
            #pragma unroll
            for (int i = 0; i < 4; i++) qv[i] = Qs[(ty * 4 + i) * 65 + kk];
            #pragma unroll
            for (int j = 0; j < 4; j++) kv[j] = Ks[(tx * 4 + j) * 65 + kk];
            #pragma unroll
            for (int i = 0; i < 4; i++)
                #pragma unroll
                for (int j = 0; j < 4; j++)
                    s4[i][j] += qv[i] * kv[j];
        }

        if (kt == qt) {
            #pragma unroll
            for (int i = 0; i < 4; i++)
                #pragma unroll
                for (int j = 0; j < 4; j++)
                    if (tx * 4 + j > ty * 4 + i) s4[i][j] = -1e30f;
        }

        float p4[4][4];
        #pragma unroll
        for (int i = 0; i < 4; i++) {
            float mt = s4[i][0];
            #pragma unroll
            for (int j = 1; j < 4; j++) mt = fmaxf(mt, s4[i][j]);
            #pragma unroll
            for (int off = 8; off; off >>= 1)
                mt = fmaxf(mt, __shfl_xor_sync(0xffffffffu, mt, off));
            const float mnew = fmaxf(m_old[i], mt);
            const float alpha = __expf(m_old[i] - mnew);
            float r = 0.0f;
            #pragma unroll
            for (int j = 0; j < 4; j++) {
                p4[i][j] = __expf(s4[i][j] - mnew);
                r += p4[i][j];
            }
            #pragma unroll
            for (int off = 8; off; off >>= 1)
                r += __shfl_xor_sync(0xffffffffu, r, off);
            lsum[i] = lsum[i] * alpha + r;
            m_old[i] = mnew;
            #pragma unroll
            for (int j = 0; j < 4; j++) o[i][j] *= alpha;
        }

        __syncthreads();
        #pragma unroll
        for (int i = 0; i < 4; i++)
            #pragma unroll
            for (int j = 0; j < 4; j++)
                Ks[(tx * 4 + j) * 65 + ty * 4 + i] = p4[i][j];
        __syncthreads();

        #pragma unroll 4
        for (int kk = 0; kk < 64; kk++) {
            float pv[4], vv[4];
            #pragma unroll
            for (int i = 0; i < 4; i++) pv[i] = Ks[kk * 65 + ty * 4 + i];
            #pragma unroll
            for (int j = 0; j < 4; j++) vv[j] = Vs[kk * 64 + tx * 4 + j];
            #pragma unroll
            for (int i = 0; i < 4; i++)
                #pragma unroll
                for (int j = 0; j < 4; j++)
                    o[i][j] += pv[i] * vv[j];
        }
    }

    #pragma unroll
    for (int i = 0; i < 4; i++) {
        const long long row = (long long)(b * T_SEQ + qt * 64 + ty * 4 + i);
        __half* obase = ctxh + row * D_MOD + h * HDIM + tx * 4;
        const float inv_l = 1.0f / lsum[i];
        __half2 v0 = __floats2half2_rn(o[i][0] * inv_l, o[i][1] * inv_l);
        __half2 v1 = __floats2half2_rn(o[i][2] * inv_l, o[i][3] * inv_l);
        *(__half2*)(obase + 0) = v0;
        *(__half2*)(obase + 2) = v1;
    }
}

// ---------------------------------------------------------------------------
// Launch
// ---------------------------------------------------------------------------
extern "C" void kernel_launch(void* const* d_in, const int* in_sizes, int n_in,
                              void* d_out, int out_size)
{
    const float* x  = (const float*)d_in[0];
    const float* Wq = (const float*)d_in[4];
    const float* bq = (const float*)d_in[5];
    const float* Wk = (const float*)d_in[6];
    const float* bk = (const float*)d_in[7];
    const float* Wv = (const float*)d_in[8];
    const float* bv = (const float*)d_in[9];
    const float* Wo = (const float*)d_in[10];
    const float* bo = (const float*)d_in[11];

    float* out = (float*)d_out;
    float* cache_out = out + (size_t)M_ROWS * D_MOD;

    __half* xh = nullptr; __half* wh = nullptr; __half* ctxh = nullptr;
    float* qbuf = nullptr;
    cudaGetSymbolAddress((void**)&xh, g_xh);
    cudaGetSymbolAddress((void**)&wh, g_wh);
    cudaGetSymbolAddress((void**)&ctxh, g_ctxh);
    cudaGetSymbolAddress((void**)&qbuf, g_q);

    const int smem_gemm = STAGES * STAGE_BYTES + 1024;   // 132 KB
    const int smem_attn = (64 * 65 + 64 * 65 + 64 * 64) * sizeof(float);
    cudaFuncSetAttribute(gemm_hmma_kernel, cudaFuncAttributeMaxDynamicSharedMemorySize, smem_gemm);
    cudaFuncSetAttribute(attn_kernel, cudaFuncAttributeMaxDynamicSharedMemorySize, smem_attn);

    const size_t WSZ = (size_t)D_MOD * D_MOD;
    const long long TN = (long long)T_SEQ * D_MOD;

    // 1) prep: x -> fp16, W -> fp16 [N][K] x4
    convert_x_kernel<<<(M_ROWS * D_MOD) / (256 * 4), 256>>>(x, xh);
    dim3 tgrid(D_MOD / 32, D_MOD / 32, 4);
    convert_wt_kernel<<<tgrid, 256>>>(Wq, Wk, Wv, Wo, wh);

    dim3 ggrid(D_MOD / 128, M_ROWS / 128);   // (16, 32)

    // 2) projections (tensor cores, fp16 in / fp32 out)
    gemm_hmma_kernel<<<ggrid, 256, smem_gemm>>>(xh, wh + 0 * WSZ, bq, qbuf, TN, 0);
    gemm_hmma_kernel<<<ggrid, 256, smem_gemm>>>(xh, wh + 1 * WSZ, bk, cache_out, 2 * TN, 0);
    gemm_hmma_kernel<<<ggrid, 256, smem_gemm>>>(xh, wh + 2 * WSZ, bv, cache_out, 2 * TN, TN);

    // 3) causal flash attention (fp32, fp16 ctx out)
    dim3 agrid(T_SEQ / 64, NHEAD, BATCH);
    attn_kernel<<<agrid, 256, smem_attn>>>(qbuf, cache_out, ctxh);

    // 4) output projection
    gemm_hmma_kernel<<<ggrid, 256, smem_gemm>>>(ctxh, wh + 3 * WSZ, bo, out, TN, 0);
}

// round 5
// speedup vs baseline: 7.1314x; 2.0009x over previous
#include <cuda_runtime.h>
#include <cuda_fp16.h>
#include <cstdint>

// Problem constants
#define BATCH 4
#define T_SEQ 1024
#define D_MOD 2048
#define NHEAD 32
#define HDIM  64
#define M_ROWS (BATCH * T_SEQ)      // 4096

#define STAGES 4
#define BK 64                       // fp16 K-slab (128 bytes per row)
#define NSLAB (D_MOD / BK)          // 32
#define STAGE_BYTES 32768           // (128*64 + 128*64) * 2
#define TNLL ((long long)T_SEQ * D_MOD)

// Scratch (device globals; allocation-free per harness rules)
__device__ __half g_xh[(size_t)M_ROWS * D_MOD];          // x fp16 [M][K]
__device__ __half g_wh[4ull * D_MOD * D_MOD];            // weights fp16 [N][K] x4 (q,k,v,o)
__device__ __half g_qh[(size_t)M_ROWS * D_MOD];          // Q*scale fp16
__device__ __half g_kh[(size_t)M_ROWS * D_MOD];          // K fp16
__device__ __half g_vh[(size_t)M_ROWS * D_MOD];          // V fp16
__device__ __half g_ctxh[(size_t)M_ROWS * D_MOD];        // attn ctx fp16

// ---------------------------------------------------------------------------
// helpers
// ---------------------------------------------------------------------------
__device__ __forceinline__ uint32_t smem_u32(const void* p) {
    return (uint32_t)__cvta_generic_to_shared(p);
}
#define SWZ(o) ((o) ^ (((o) >> 3) & 0x70))

__device__ __forceinline__ void cp16(uint32_t dst, const void* src) {
    asm volatile("cp.async.cg.shared.global [%0], [%1], 16;" :: "r"(dst), "l"(src));
}
__device__ __forceinline__ void ldmx4(uint32_t* r, uint32_t addr) {
    asm volatile("ldmatrix.sync.aligned.m8n8.x4.shared.b16 {%0,%1,%2,%3}, [%4];"
                 : "=r"(r[0]), "=r"(r[1]), "=r"(r[2]), "=r"(r[3]) : "r"(addr));
}
__device__ __forceinline__ void ldmx4t(uint32_t* r, uint32_t addr) {
    asm volatile("ldmatrix.sync.aligned.m8n8.x4.trans.shared.b16 {%0,%1,%2,%3}, [%4];"
                 : "=r"(r[0]), "=r"(r[1]), "=r"(r[2]), "=r"(r[3]) : "r"(addr));
}
__device__ __forceinline__ void mma16816(float* c, const uint32_t* a,
                                         uint32_t b0, uint32_t b1) {
    asm volatile(
        "mma.sync.aligned.m16n8k16.row.col.f32.f16.f16.f32 "
        "{%0,%1,%2,%3}, {%4,%5,%6,%7}, {%8,%9}, {%0,%1,%2,%3};"
        : "+f"(c[0]), "+f"(c[1]), "+f"(c[2]), "+f"(c[3])
        : "r"(a[0]), "r"(a[1]), "r"(a[2]), "r"(a[3]), "r"(b0), "r"(b1));
}

// ---------------------------------------------------------------------------
// Prep: x (f32) -> fp16
// ---------------------------------------------------------------------------
__global__ __launch_bounds__(256)
void convert_x_kernel(const float* __restrict__ x, __half* __restrict__ xh)
{
    const size_t i = (size_t)blockIdx.x * 256 + threadIdx.x;
    float4 v = ((const float4*)x)[i];
    __half2* o = (__half2*)xh;
    o[i * 2 + 0] = __floats2half2_rn(v.x, v.y);
    o[i * 2 + 1] = __floats2half2_rn(v.z, v.w);
}

// ---------------------------------------------------------------------------
// Prep: W [K][N] f32 -> Wh [N][K] fp16 (transpose + convert), 4 matrices
// ---------------------------------------------------------------------------
__global__ __launch_bounds__(256)
void convert_wt_kernel(const float* __restrict__ w0, const float* __restrict__ w1,
                       const float* __restrict__ w2, const float* __restrict__ w3,
                       __half* __restrict__ dst)
{
    __shared__ float tile[32][33];
    const float* src = blockIdx.z == 0 ? w0 : blockIdx.z == 1 ? w1
                     : blockIdx.z == 2 ? w2 : w3;
    __half* d = dst + (size_t)blockIdx.z * D_MOD * D_MOD;
    const int tx = threadIdx.x & 31, ty = threadIdx.x >> 5;
    const int n0 = blockIdx.x * 32, k0 = blockIdx.y * 32;
    #pragma unroll
    for (int r = 0; r < 32; r += 8)
        tile[ty + r][tx] = src[(size_t)(k0 + ty + r) * D_MOD + n0 + tx];
    __syncthreads();
    #pragma unroll
    for (int r = 0; r < 32; r += 8)
        d[(size_t)(n0 + ty + r) * D_MOD + k0 + tx] = __float2half(tile[tx][ty + r]);
}

// ---------------------------------------------------------------------------
// GEMM mainloop (shared by both gemm kernels): acc = A[128 rows of bm] @ B^T
// ---------------------------------------------------------------------------
#define GEMM_MAINLOOP(Ab, Bb, sbase, acc)                                       \
    {                                                                           \
        _Pragma("unroll")                                                       \
        for (int s = 0; s < STAGES - 1; s++) {                                  \
            const uint32_t stA = sbase + s * STAGE_BYTES;                       \
            const uint32_t stB = stA + 16384u;                                  \
            const int kb = s * BK;                                              \
            _Pragma("unroll")                                                   \
            for (int t = 0; t < 4; t++) {                                       \
                const int c = tid + t * 256;                                    \
                const int r = c >> 3, u = c & 7;                                \
                cp16(stA + SWZ((uint32_t)(r * 128 + u * 16)), Ab + (size_t)r * D_MOD + kb + u * 8); \
                cp16(stB + SWZ((uint32_t)(r * 128 + u * 16)), Bb + (size_t)r * D_MOD + kb + u * 8); \
            }                                                                   \
            asm volatile("cp.async.commit_group;" ::: "memory");                \
        }                                                                       \
        const int lrow = lane & 15;                                             \
        const int lcol = (lane >> 4) * 16;                                      \
        for (int i = 0; i < NSLAB; i++) {                                       \
            asm volatile("cp.async.wait_group %0;" :: "n"(STAGES - 2) : "memory"); \
            __syncthreads();                                                    \
            if (i + STAGES - 1 < NSLAB) {                                       \
                const int s = (i + STAGES - 1) & (STAGES - 1);                  \
                const uint32_t stA = sbase + s * STAGE_BYTES;                   \
                const uint32_t stB = stA + 16384u;                              \
                const int kb = (i + STAGES - 1) * BK;                           \
                _Pragma("unroll")                                               \
                for (int t = 0; t < 4; t++) {                                   \
                    const int c = tid + t * 256;                                \
                    const int r = c >> 3, u = c & 7;                            \
                    cp16(stA + SWZ((uint32_t)(r * 128 + u * 16)), Ab + (size_t)r * D_MOD + kb + u * 8); \
                    cp16(stB + SWZ((uint32_t)(r * 128 + u * 16)), Bb + (size_t)r * D_MOD + kb + u * 8); \
                }                                                               \
            }                                                                   \
            asm volatile("cp.async.commit_group;" ::: "memory");                \
            const int s = i & (STAGES - 1);                                     \
            const uint32_t stA = sbase + s * STAGE_BYTES;                       \
            const uint32_t stB = stA + 16384u;                                  \
            _Pragma("unroll")                                                   \
            for (int ks = 0; ks < BK / 16; ks++) {                              \
                uint32_t afr[4][4], bfr[2][4];                                  \
                _Pragma("unroll")                                               \
                for (int mt = 0; mt < 4; mt++)                                  \
                    ldmx4(afr[mt], stA + SWZ((uint32_t)((wm * 64 + mt * 16 + lrow) * 128 + ks * 32 + lcol))); \
                _Pragma("unroll")                                               \
                for (int bt = 0; bt < 2; bt++)                                  \
                    ldmx4(bfr[bt], stB + SWZ((uint32_t)((wn * 32 + bt * 16 + lrow) * 128 + ks * 32 + lcol))); \
                _Pragma("unroll")                                               \
                for (int mt = 0; mt < 4; mt++)                                  \
                    _Pragma("unroll")                                           \
                    for (int nt = 0; nt < 4; nt++) {                            \
                        const int bt = nt >> 1, sub = nt & 1;                   \
                        mma16816(acc[mt][nt], afr[mt], bfr[bt][sub], bfr[bt][sub + 2]); \
                    }                                                           \
            }                                                                   \
            __syncthreads();                                                    \
        }                                                                       \
    }

// ---------------------------------------------------------------------------
// Fused QKV projection GEMM. grid = (48, 32). bn segment: 0-15 Q, 16-31 K, 32-47 V.
// Q -> g_qh fp16 (scaled 0.125). K/V -> cache f32 (remapped) + fp16 copies.
// ---------------------------------------------------------------------------
__global__ __launch_bounds__(256, 1)
void gemm_qkv_kernel(const __half* __restrict__ A, const __half* __restrict__ B,
                     const float* __restrict__ bq, const float* __restrict__ bk,
                     const float* __restrict__ bv, float* __restrict__ cache,
                     __half* __restrict__ qh, __half* __restrict__ kh,
                     __half* __restrict__ vh)
{
    extern __shared__ char dsmem_raw[];
    __shared__ float bias_s[128];

    const int tid  = threadIdx.x;
    const int lane = tid & 31;
    const int wid  = tid >> 5;
    const int wm   = wid & 1;
    const int wn   = wid >> 1;
    const int bm = blockIdx.y, bn = blockIdx.x;
    const int seg = bn >> 4;           // 0=q 1=k 2=v
    const int bnn = bn & 15;

    uint32_t sbase = smem_u32(dsmem_raw);
    sbase = (sbase + 1023u) & ~1023u;

    const float* bp = seg == 0 ? bq : seg == 1 ? bk : bv;
    if (tid < 128) bias_s[tid] = bp[bnn * 128 + tid];

    const __half* Ab = A + (size_t)bm * 128 * D_MOD;
    const __half* Bb = B + (size_t)bn * 128 * D_MOD;

    float acc[4][4][4];
    #pragma unroll
    for (int i = 0; i < 4; i++)
        #pragma unroll
        for (int j = 0; j < 4; j++)
            #pragma unroll
            for (int q = 0; q < 4; q++) acc[i][j][q] = 0.0f;

    GEMM_MAINLOOP(Ab, Bb, sbase, acc)

    __half* hout = seg == 0 ? qh : seg == 1 ? kh : vh;
    const float hscale = seg == 0 ? 0.125f : 1.0f;

    const int g = lane >> 2, t2 = (lane & 3) * 2;
    #pragma unroll
    for (int mt = 0; mt < 4; mt++) {
        #pragma unroll
        for (int hm = 0; hm < 2; hm++) {
            const int row_g = bm * 128 + wm * 64 + mt * 16 + hm * 8 + g;
            __half* Hrow = hout + (size_t)row_g * D_MOD + bnn * 128;
            float* Crow = nullptr;
            if (seg) {
                const int bb = row_g >> 10, tt = row_g & 1023;
                Crow = cache + (long long)bb * 2 * TNLL + (seg == 2 ? TNLL : 0)
                             + (long long)tt * D_MOD + bnn * 128;
            }
            #pragma unroll
            for (int nt = 0; nt < 4; nt++) {
                const int col = wn * 32 + nt * 8 + t2;
                float2 v;
                v.x = acc[mt][nt][hm * 2 + 0] + bias_s[col];
                v.y = acc[mt][nt][hm * 2 + 1] + bias_s[col + 1];
                *(__half2*)(Hrow + col) = __floats2half2_rn(v.x * hscale, v.y * hscale);
                if (seg) *(float2*)(Crow + col) = v;
            }
        }
    }
}

// ---------------------------------------------------------------------------
// Output projection GEMM: out(f32) = ctxh @ WoT^T + bo. grid = (16, 32).
// ---------------------------------------------------------------------------
__global__ __launch_bounds__(256, 1)
void gemm_out_kernel(const __half* __restrict__ A, const __half* __restrict__ B,
                     const float* __restrict__ bias, float* __restrict__ C)
{
    extern __shared__ char dsmem_raw[];
    __shared__ float bias_s[128];

    const int tid  = threadIdx.x;
    const int lane = tid & 31;
    const int wid  = tid >> 5;
    const int wm   = wid & 1;
    const int wn   = wid >> 1;
    const int bm = blockIdx.y, bn = blockIdx.x;

    uint32_t sbase = smem_u32(dsmem_raw);
    sbase = (sbase + 1023u) & ~1023u;

    if (tid < 128) bias_s[tid] = bias[bn * 128 + tid];

    const __half* Ab = A + (size_t)bm * 128 * D_MOD;
    const __half* Bb = B + (size_t)bn * 128 * D_MOD;

    float acc[4][4][4];
    #pragma unroll
    for (int i = 0; i < 4; i++)
        #pragma unroll
        for (int j = 0; j < 4; j++)
            #pragma unroll
            for (int q = 0; q < 4; q++) acc[i][j][q] = 0.0f;

    GEMM_MAINLOOP(Ab, Bb, sbase, acc)

    const int g = lane >> 2, t2 = (lane & 3) * 2;
    #pragma unroll
    for (int mt = 0; mt < 4; mt++) {
        #pragma unroll
        for (int hm = 0; hm < 2; hm++) {
            const int row_g = bm * 128 + wm * 64 + mt * 16 + hm * 8 + g;
            float* Crow = C + (size_t)row_g * D_MOD + bn * 128;
            #pragma unroll
            for (int nt = 0; nt < 4; nt++) {
                const int col = wn * 32 + nt * 8 + t2;
                float2 v;
                v.x = acc[mt][nt][hm * 2 + 0] + bias_s[col];
                v.y = acc[mt][nt][hm * 2 + 1] + bias_s[col + 1];
                *(float2*)(Crow + col) = v;
            }
        }
    }
}

// ---------------------------------------------------------------------------
// HMMA flash attention (causal). CTA = 128 queries of one (b,h), 256 thr / 8 warps.
// Warp owns 16 q-rows. Online softmax fp32; P reused from accumulators as
// fp16 A-fragments (no smem round trip). V via ldmatrix.x4.trans.
// smem: Q 16KB + 2 stages x (K 16KB + V 16KB) = 80KB.
// ---------------------------------------------------------------------------
__global__ __launch_bounds__(256, 1)
void attn_hmma_kernel(const __half* __restrict__ qh, const __half* __restrict__ kh,
                      const __half* __restrict__ vh, __half* __restrict__ ctxh)
{
    extern __shared__ char dsmem_raw[];
    uint32_t sbase = smem_u32(dsmem_raw);
    sbase = (sbase + 1023u) & ~1023u;
    const uint32_t Qsm = sbase;

    const int qt = (int)(gridDim.x - 1 - blockIdx.x);   // reversed: heavy CTAs first
    const int h  = blockIdx.y;
    const int b  = blockIdx.z;
    const int tid = threadIdx.x;
    const int lane = tid & 31;
    const int wid  = tid >> 5;
    const int m0   = wid * 16;

    const size_t bh_off = ((size_t)b * T_SEQ) * D_MOD + h * HDIM;
    const __half* Qg = qh + bh_off + (size_t)qt * 128 * D_MOD;
    const __half* Kg = kh + bh_off;
    const __half* Vg = vh + bh_off;

    // prologue: Q + (K,V) tile 0 in one group
    #pragma unroll
    for (int t = 0; t < 4; t++) {
        const int c = tid + t * 256;
        const int r = c >> 3, u = c & 7;
        cp16(Qsm + SWZ((uint32_t)(r * 128 + u * 16)), Qg + (size_t)r * D_MOD + u * 8);
    }
    {
        const uint32_t Kst = sbase + 16384u, Vst = Kst + 16384u;
        #pragma unroll
        for (int t = 0; t < 4; t++) {
            const int c = tid + t * 256;
            const int r = c >> 3, u = c & 7;
            cp16(Kst + SWZ((uint32_t)(r * 128 + u * 16)), Kg + (size_t)r * D_MOD + u * 8);
            cp16(Vst + SWZ((uint32_t)(r * 128 + u * 16)), Vg + (size_t)r * D_MOD + u * 8);
        }
        asm volatile("cp.async.commit_group;" ::: "memory");
    }

    const int lrow = lane & 15;
    const int lcol = (lane >> 4) * 16;

    uint32_t qf[4][4];
    float oacc[8][4];
    #pragma unroll
    for (int j = 0; j < 8; j++)
        #pragma unroll
        for (int q = 0; q < 4; q++) oacc[j][q] = 0.0f;
    float mrun0 = -1e30f, mrun1 = -1e30f, lrun0 = 0.0f, lrun1 = 0.0f;

    for (int i = 0; i <= qt; i++) {
        const int s = i & 1;
        if (i + 1 <= qt) {
            const uint32_t Kst = sbase + 16384u + (uint32_t)(s ^ 1) * 32768u;
            const uint32_t Vst = Kst + 16384u;
            const __half* Kn = Kg + (size_t)(i + 1) * 128 * D_MOD;
            const __half* Vn = Vg + (size_t)(i + 1) * 128 * D_MOD;
            #pragma unroll
            for (int t = 0; t < 4; t++) {
                const int c = tid + t * 256;
                const int r = c >> 3, u = c & 7;
                cp16(Kst + SWZ((uint32_t)(r * 128 + u * 16)), Kn + (size_t)r * D_MOD + u * 8);
                cp16(Vst + SWZ((uint32_t)(r * 128 + u * 16)), Vn + (size_t)r * D_MOD + u * 8);
            }
            asm volatile("cp.async.commit_group;" ::: "memory");
            asm volatile("cp.async.wait_group 1;" ::: "memory");
        } else {
            asm volatile("cp.async.wait_group 0;" ::: "memory");
        }
        __syncthreads();

        if (i == 0) {
            #pragma unroll
            for (int ks = 0; ks < 4; ks++)
                ldmx4(qf[ks], Qsm + SWZ((uint32_t)((m0 + lrow) * 128 + ks * 32 + lcol)));
        }

        const uint32_t Kst = sbase + 16384u + (uint32_t)s * 32768u;
        const uint32_t Vst = Kst + 16384u;

        // S = Q @ K^T : 16 q-rows x 128 keys per warp
        float sacc[16][4];
        #pragma unroll
        for (int nt = 0; nt < 16; nt++)
            #pragma unroll
            for (int q = 0; q < 4; q++) sacc[nt][q] = 0.0f;

        #pragma unroll
        for (int gblk = 0; gblk < 8; gblk++) {       // 16 keys per block
            #pragma unroll
            for (int ks = 0; ks < 4; ks++) {
                uint32_t kf[4];
                ldmx4(kf, Kst + SWZ((uint32_t)((gblk * 16 + lrow) * 128 + ks * 32 + lcol)));
                mma16816(sacc[gblk * 2 + 0], qf[ks], kf[0], kf[2]);
                mma16816(sacc[gblk * 2 + 1], qf[ks], kf[1], kf[3]);
            }
        }

        // causal mask on diagonal tile
        if (i == qt) {
            const int row0 = m0 + (lane >> 2);
            #pragma unroll
            for (int nt = 0; nt < 16; nt++) {
                const int cb = nt * 8 + (lane & 3) * 2;
                if (cb + 0 > row0) sacc[nt][0] = -1e30f;
                if (cb + 1 > row0) sacc[nt][1] = -1e30f;
                if (cb + 0 > row0 + 8) sacc[nt][2] = -1e30f;
                if (cb + 1 > row0 + 8) sacc[nt][3] = -1e30f;
            }
        }

        // online softmax (rows r = lane>>2 and r+8 of this warp's 16)
        float mx0 = -1e30f, mx1 = -1e30f;
        #pragma unroll
        for (int nt = 0; nt < 16; nt++) {
            mx0 = fmaxf(mx0, fmaxf(sacc[nt][0], sacc[nt][1]));
            mx1 = fmaxf(mx1, fmaxf(sacc[nt][2], sacc[nt][3]));
        }
        mx0 = fmaxf(mx0, __shfl_xor_sync(0xffffffffu, mx0, 1));
        mx0 = fmaxf(mx0, __shfl_xor_sync(0xffffffffu, mx0, 2));
        mx1 = fmaxf(mx1, __shfl_xor_sync(0xffffffffu, mx1, 1));
        mx1 = fmaxf(mx1, __shfl_xor_sync(0xffffffffu, mx1, 2));

        const float mnew0 = fmaxf(mrun0, mx0);
        const float mnew1 = fmaxf(mrun1, mx1);
        const float alpha0 = __expf(mrun0 - mnew0);
        const float alpha1 = __expf(mrun1 - mnew1);

        float sum0 = 0.0f, sum1 = 0.0f;
        #pragma unroll
        for (int nt = 0; nt < 16; nt++) {
            sacc[nt][0] = __expf(sacc[nt][0] - mnew0);
            sacc[nt][1] = __expf(sacc[nt][1] - mnew0);
            sacc[nt][2] = __expf(sacc[nt][2] - mnew1);
            sacc[nt][3] = __expf(sacc[nt][3] - mnew1);
            sum0 += sacc[nt][0] + sacc[nt][1];
            sum1 += sacc[nt][2] + sacc[nt][3];
        }
        sum0 += __shfl_xor_sync(0xffffffffu, sum0, 1);
        sum0 += __shfl_xor_sync(0xffffffffu, sum0, 2);
        sum1 += __shfl_xor_sync(0xffffffffu, sum1, 1);
        sum1 += __shfl_xor_sync(0xffffffffu, sum1, 2);

        lrun0 = lrun0 * alpha0 + sum0;
        lrun1 = lrun1 * alpha1 + sum1;
        mrun0 = mnew0; mrun1 = mnew1;

        #pragma unroll
        for (int j = 0; j < 8; j++) {
            oacc[j][0] *= alpha0; oacc[j][1] *= alpha0;
            oacc[j][2] *= alpha1; oacc[j][3] *= alpha1;
        }

        // O += P @ V  (P from sacc accumulators, V via ldmatrix trans)
        #pragma unroll
        for (int ksv = 0; ksv < 8; ksv++) {          // 16 keys per step
            uint32_t paf[4];
            __half2 h0 = __floats2half2_rn(sacc[2 * ksv][0], sacc[2 * ksv][1]);
            __half2 h1 = __floats2half2_rn(sacc[2 * ksv][2], sacc[2 * ksv][3]);
            __half2 h2 = __floats2half2_rn(sacc[2 * ksv + 1][0], sacc[2 * ksv + 1][1]);
            __half2 h3 = __floats2half2_rn(sacc[2 * ksv + 1][2], sacc[2 * ksv + 1][3]);
            paf[0] = *(uint32_t*)&h0;
            paf[1] = *(uint32_t*)&h1;
            paf[2] = *(uint32_t*)&h2;
            paf[3] = *(uint32_t*)&h3;
            #pragma unroll
            for (int j = 0; j < 4; j++) {            // 16 hd cols per trans load
                uint32_t vf[4];
                ldmx4t(vf, Vst + SWZ((uint32_t)((ksv * 16 + lrow) * 128 + j * 32 + lcol)));
                mma16816(oacc[2 * j + 0], paf, vf[0], vf[1]);
                mma16816(oacc[2 * j + 1], paf, vf[2], vf[3]);
            }
        }
        __syncthreads();
    }

    // epilogue: normalize, write ctx fp16 (merged layout)
    const float inv0 = 1.0f / lrun0;
    const float inv1 = 1.0f / lrun1;
    const int r0 = qt * 128 + m0 + (lane >> 2);
    __half* C0 = ctxh + ((size_t)b * T_SEQ + r0) * D_MOD + h * HDIM + (lane & 3) * 2;
    __half* C1 = C0 + 8ull * D_MOD;
    #pragma unroll
    for (int j = 0; j < 8; j++) {
        *(__half2*)(C0 + j * 8) = __floats2half2_rn(oacc[j][0] * inv0, oacc[j][1] * inv0);
        *(__half2*)(C1 + j * 8) = __floats2half2_rn(oacc[j][2] * inv1, oacc[j][3] * inv1);
    }
}

// ---------------------------------------------------------------------------
// Launch
// ---------------------------------------------------------------------------
extern "C" void kernel_launch(void* const* d_in, const int* in_sizes, int n_in,
                              void* d_out, int out_size)
{
    const float* x  = (const float*)d_in[0];
    const float* Wq = (const float*)d_in[4];
    const float* bq = (const float*)d_in[5];
    const float* Wk = (const float*)d_in[6];
    const float* bk = (const float*)d_in[7];
    const float* Wv = (const float*)d_in[8];
    const float* bv = (const float*)d_in[9];
    const float* Wo = (const float*)d_in[10];
    const float* bo = (const float*)d_in[11];

    float* out = (float*)d_out;
    float* cache_out = out + (size_t)M_ROWS * D_MOD;

    __half *xh, *wh, *qh, *kh, *vh, *ctxh;
    cudaGetSymbolAddress((void**)&xh, g_xh);
    cudaGetSymbolAddress((void**)&wh, g_wh);
    cudaGetSymbolAddress((void**)&qh, g_qh);
    cudaGetSymbolAddress((void**)&kh, g_kh);
    cudaGetSymbolAddress((void**)&vh, g_vh);
    cudaGetSymbolAddress((void**)&ctxh, g_ctxh);

    const int smem_gemm = STAGES * STAGE_BYTES + 1024;          // 132 KB
    const int smem_attn = 16384 + 2 * 32768 + 1024;             // 82 KB
    cudaFuncSetAttribute(gemm_qkv_kernel, cudaFuncAttributeMaxDynamicSharedMemorySize, smem_gemm);
    cudaFuncSetAttribute(gemm_out_kernel, cudaFuncAttributeMaxDynamicSharedMemorySize, smem_gemm);
    cudaFuncSetAttribute(attn_hmma_kernel, cudaFuncAttributeMaxDynamicSharedMemorySize, smem_attn);

    const size_t WSZ = (size_t)D_MOD * D_MOD;

    // 1) prep
    convert_x_kernel<<<(M_ROWS * D_MOD) / (256 * 4), 256>>>(x, xh);
    dim3 tgrid(D_MOD / 32, D_MOD / 32, 4);
    convert_wt_kernel<<<tgrid, 256>>>(Wq, Wk, Wv, Wo, wh);

    // 2) fused QKV projection
    dim3 qkvgrid(48, 32);
    gemm_qkv_kernel<<<qkvgrid, 256, smem_gemm>>>(xh, wh, bq, bk, bv,
                                                 cache_out, qh, kh, vh);

    // 3) HMMA causal flash attention
    dim3 agrid(T_SEQ / 128, NHEAD, BATCH);   // (8, 32, 4)
    attn_hmma_kernel<<<agrid, 256, smem_attn>>>(qh, kh, vh, ctxh);

    // 4) output projection
    dim3 ogrid(16, 32);
    gemm_out_kernel<<<ogrid, 256, smem_gemm>>>(ctxh, wh + 3 * WSZ, bo, out);
}

// round 6
// speedup vs baseline: 7.9736x; 1.1181x over previous
#include <cuda_runtime.h>
#include <cuda_fp16.h>
#include <cstdint>

// Problem constants
#define BATCH 4
#define T_SEQ 1024
#define D_MOD 2048
#define NHEAD 32
#define HDIM  64
#define M_ROWS (BATCH * T_SEQ)      // 4096

#define STAGES 3
#define BK 64                       // fp16 K-slab (128 bytes per row)
#define NSLAB (D_MOD / BK)          // 32
#define STAGE_BYTES 32768           // (128*64 + 128*64) * 2
#define TNLL ((long long)T_SEQ * D_MOD)

// Scratch (device globals; allocation-free per harness rules)
__device__ __half g_xh[(size_t)M_ROWS * D_MOD];          // x fp16 [M][K]
__device__ __half g_wh[4ull * D_MOD * D_MOD];            // weights fp16 [N][K] x4 (q,k,v,o)
__device__ __half g_qh[(size_t)M_ROWS * D_MOD];          // Q*scale fp16
__device__ __half g_kh[(size_t)M_ROWS * D_MOD];          // K fp16
__device__ __half g_vh[(size_t)M_ROWS * D_MOD];          // V fp16
__device__ __half g_ctxh[(size_t)M_ROWS * D_MOD];        // attn ctx fp16

// ---------------------------------------------------------------------------
// helpers
// ---------------------------------------------------------------------------
__device__ __forceinline__ uint32_t smem_u32(const void* p) {
    return (uint32_t)__cvta_generic_to_shared(p);
}
#define SWZ(o) ((o) ^ (((o) >> 3) & 0x70))

__device__ __forceinline__ void cp16(uint32_t dst, const void* src) {
    asm volatile("cp.async.cg.shared.global [%0], [%1], 16;" :: "r"(dst), "l"(src));
}
__device__ __forceinline__ void ldmx4(uint32_t* r, uint32_t addr) {
    asm volatile("ldmatrix.sync.aligned.m8n8.x4.shared.b16 {%0,%1,%2,%3}, [%4];"
                 : "=r"(r[0]), "=r"(r[1]), "=r"(r[2]), "=r"(r[3]) : "r"(addr));
}
__device__ __forceinline__ void ldmx4t(uint32_t* r, uint32_t addr) {
    asm volatile("ldmatrix.sync.aligned.m8n8.x4.trans.shared.b16 {%0,%1,%2,%3}, [%4];"
                 : "=r"(r[0]), "=r"(r[1]), "=r"(r[2]), "=r"(r[3]) : "r"(addr));
}
__device__ __forceinline__ void mma16816(float* c, const uint32_t* a,
                                         uint32_t b0, uint32_t b1) {
    asm volatile(
        "mma.sync.aligned.m16n8k16.row.col.f32.f16.f16.f32 "
        "{%0,%1,%2,%3}, {%4,%5,%6,%7}, {%8,%9}, {%0,%1,%2,%3};"
        : "+f"(c[0]), "+f"(c[1]), "+f"(c[2]), "+f"(c[3])
        : "r"(a[0]), "r"(a[1]), "r"(a[2]), "r"(a[3]), "r"(b0), "r"(b1));
}

// ---------------------------------------------------------------------------
// Prep: x (f32) -> fp16
// ---------------------------------------------------------------------------
__global__ __launch_bounds__(256)
void convert_x_kernel(const float* __restrict__ x, __half* __restrict__ xh)
{
    const size_t i = (size_t)blockIdx.x * 256 + threadIdx.x;
    float4 v = ((const float4*)x)[i];
    __half2* o = (__half2*)xh;
    o[i * 2 + 0] = __floats2half2_rn(v.x, v.y);
    o[i * 2 + 1] = __floats2half2_rn(v.z, v.w);
}

// ---------------------------------------------------------------------------
// Prep: W [K][N] f32 -> Wh [N][K] fp16 (transpose + convert), 4 matrices
// ---------------------------------------------------------------------------
__global__ __launch_bounds__(256)
void convert_wt_kernel(const float* __restrict__ w0, const float* __restrict__ w1,
                       const float* __restrict__ w2, const float* __restrict__ w3,
                       __half* __restrict__ dst)
{
    __shared__ float tile[32][33];
    const float* src = blockIdx.z == 0 ? w0 : blockIdx.z == 1 ? w1
                     : blockIdx.z == 2 ? w2 : w3;
    __half* d = dst + (size_t)blockIdx.z * D_MOD * D_MOD;
    const int tx = threadIdx.x & 31, ty = threadIdx.x >> 5;
    const int n0 = blockIdx.x * 32, k0 = blockIdx.y * 32;
    #pragma unroll
    for (int r = 0; r < 32; r += 8)
        tile[ty + r][tx] = src[(size_t)(k0 + ty + r) * D_MOD + n0 + tx];
    __syncthreads();
    #pragma unroll
    for (int r = 0; r < 32; r += 8)
        d[(size_t)(n0 + ty + r) * D_MOD + k0 + tx] = __float2half(tile[tx][ty + r]);
}

// ---------------------------------------------------------------------------
// GEMM mainloop: 3-stage cp.async pipeline, one __syncthreads per iteration.
// ---------------------------------------------------------------------------
#define GEMM_MAINLOOP(Ab, Bb, sbase, acc)                                       \
    {                                                                           \
        _Pragma("unroll")                                                       \
        for (int s = 0; s < STAGES - 1; s++) {                                  \
            const uint32_t stA = sbase + s * STAGE_BYTES;                       \
            const uint32_t stB = stA + 16384u;                                  \
            const int kb = s * BK;                                              \
            _Pragma("unroll")                                                   \
            for (int t = 0; t < 4; t++) {                                       \
                const int c = tid + t * 256;                                    \
                const int r = c >> 3, u = c & 7;                                \
                cp16(stA + SWZ((uint32_t)(r * 128 + u * 16)), Ab + (size_t)r * D_MOD + kb + u * 8); \
                cp16(stB + SWZ((uint32_t)(r * 128 + u * 16)), Bb + (size_t)r * D_MOD + kb + u * 8); \
            }                                                                   \
            asm volatile("cp.async.commit_group;" ::: "memory");                \
        }                                                                       \
        const int lrow = lane & 15;                                             \
        const int lcol = (lane >> 4) * 16;                                      \
        int sc = 0, sl = STAGES - 1;                                            \
        for (int i = 0; i < NSLAB; i++) {                                       \
            asm volatile("cp.async.wait_group %0;" :: "n"(STAGES - 2) : "memory"); \
            __syncthreads();                                                    \
            if (i + STAGES - 1 < NSLAB) {                                       \
                const uint32_t stA = sbase + sl * STAGE_BYTES;                  \
                const uint32_t stB = stA + 16384u;                              \
                const int kb = (i + STAGES - 1) * BK;                           \
                _Pragma("unroll")                                               \
                for (int t = 0; t < 4; t++) {                                   \
                    const int c = tid + t * 256;                                \
                    const int r = c >> 3, u = c & 7;                            \
                    cp16(stA + SWZ((uint32_t)(r * 128 + u * 16)), Ab + (size_t)r * D_MOD + kb + u * 8); \
                    cp16(stB + SWZ((uint32_t)(r * 128 + u * 16)), Bb + (size_t)r * D_MOD + kb + u * 8); \
                }                                                               \
            }                                                                   \
            asm volatile("cp.async.commit_group;" ::: "memory");                \
            sl = (sl + 1 == STAGES) ? 0 : sl + 1;                               \
            const uint32_t stA = sbase + sc * STAGE_BYTES;                      \
            const uint32_t stB = stA + 16384u;                                  \
            sc = (sc + 1 == STAGES) ? 0 : sc + 1;                               \
            _Pragma("unroll")                                                   \
            for (int ks = 0; ks < BK / 16; ks++) {                              \
                uint32_t afr[4][4], bfr[2][4];                                  \
                _Pragma("unroll")                                               \
                for (int mt = 0; mt < 4; mt++)                                  \
                    ldmx4(afr[mt], stA + SWZ((uint32_t)((wm * 64 + mt * 16 + lrow) * 128 + ks * 32 + lcol))); \
                _Pragma("unroll")                                               \
                for (int bt = 0; bt < 2; bt++)                                  \
                    ldmx4(bfr[bt], stB + SWZ((uint32_t)((wn * 32 + bt * 16 + lrow) * 128 + ks * 32 + lcol))); \
                _Pragma("unroll")                                               \
                for (int mt = 0; mt < 4; mt++)                                  \
                    _Pragma("unroll")                                           \
                    for (int nt = 0; nt < 4; nt++) {                            \
                        const int bt = nt >> 1, sub = nt & 1;                   \
                        mma16816(acc[mt][nt], afr[mt], bfr[bt][sub], bfr[bt][sub + 2]); \
                    }                                                           \
            }                                                                   \
        }                                                                       \
    }

// ---------------------------------------------------------------------------
// Fused QKV projection GEMM. grid = (48, 32). bn segment: 0-15 Q, 16-31 K, 32-47 V.
// Q -> g_qh fp16 (scaled 0.125). K/V -> cache f32 (remapped) + fp16 copies.
// ---------------------------------------------------------------------------
__global__ __launch_bounds__(256, 2)
void gemm_qkv_kernel(const __half* __restrict__ A, const __half* __restrict__ B,
                     const float* __restrict__ bq, const float* __restrict__ bk,
                     const float* __restrict__ bv, float* __restrict__ cache,
                     __half* __restrict__ qh, __half* __restrict__ kh,
                     __half* __restrict__ vh)
{
    extern __shared__ char dsmem_raw[];
    __shared__ float bias_s[128];

    const int tid  = threadIdx.x;
    const int lane = tid & 31;
    const int wid  = tid >> 5;
    const int wm   = wid & 1;
    const int wn   = wid >> 1;
    const int bm = blockIdx.y, bn = blockIdx.x;
    const int seg = bn >> 4;           // 0=q 1=k 2=v
    const int bnn = bn & 15;

    uint32_t sbase = smem_u32(dsmem_raw);
    sbase = (sbase + 1023u) & ~1023u;

    const float* bp = seg == 0 ? bq : seg == 1 ? bk : bv;
    if (tid < 128) bias_s[tid] = bp[bnn * 128 + tid];

    const __half* Ab = A + (size_t)bm * 128 * D_MOD;
    const __half* Bb = B + (size_t)bn * 128 * D_MOD;

    float acc[4][4][4];
    #pragma unroll
    for (int i = 0; i < 4; i++)
        #pragma unroll
        for (int j = 0; j < 4; j++)
            #pragma unroll
            for (int q = 0; q < 4; q++) acc[i][j][q] = 0.0f;

    GEMM_MAINLOOP(Ab, Bb, sbase, acc)

    __half* hout = seg == 0 ? qh : seg == 1 ? kh : vh;
    const float hscale = seg == 0 ? 0.125f : 1.0f;

    const int g = lane >> 2, t2 = (lane & 3) * 2;
    #pragma unroll
    for (int mt = 0; mt < 4; mt++) {
        #pragma unroll
        for (int hm = 0; hm < 2; hm++) {
            const int row_g = bm * 128 + wm * 64 + mt * 16 + hm * 8 + g;
            __half* Hrow = hout + (size_t)row_g * D_MOD + bnn * 128;
            float* Crow = nullptr;
            if (seg) {
                const int bb = row_g >> 10, tt = row_g & 1023;
                Crow = cache + (long long)bb * 2 * TNLL + (seg == 2 ? TNLL : 0)
                             + (long long)tt * D_MOD + bnn * 128;
            }
            #pragma unroll
            for (int nt = 0; nt < 4; nt++) {
                const int col = wn * 32 + nt * 8 + t2;
                float2 v;
                v.x = acc[mt][nt][hm * 2 + 0] + bias_s[col];
                v.y = acc[mt][nt][hm * 2 + 1] + bias_s[col + 1];
                *(__half2*)(Hrow + col) = __floats2half2_rn(v.x * hscale, v.y * hscale);
                if (seg) *(float2*)(Crow + col) = v;
            }
        }
    }
}

// ---------------------------------------------------------------------------
// Output projection GEMM: out(f32) = ctxh @ WoT^T + bo. grid = (16, 32).
// ---------------------------------------------------------------------------
__global__ __launch_bounds__(256, 2)
void gemm_out_kernel(const __half* __restrict__ A, const __half* __restrict__ B,
                     const float* __restrict__ bias, float* __restrict__ C)
{
    extern __shared__ char dsmem_raw[];
    __shared__ float bias_s[128];

    const int tid  = threadIdx.x;
    const int lane = tid & 31;
    const int wid  = tid >> 5;
    const int wm   = wid & 1;
    const int wn   = wid >> 1;
    const int bm = blockIdx.y, bn = blockIdx.x;

    uint32_t sbase = smem_u32(dsmem_raw);
    sbase = (sbase + 1023u) & ~1023u;

    if (tid < 128) bias_s[tid] = bias[bn * 128 + tid];

    const __half* Ab = A + (size_t)bm * 128 * D_MOD;
    const __half* Bb = B + (size_t)bn * 128 * D_MOD;

    float acc[4][4][4];
    #pragma unroll
    for (int i = 0; i < 4; i++)
        #pragma unroll
        for (int j = 0; j < 4; j++)
            #pragma unroll
            for (int q = 0; q < 4; q++) acc[i][j][q] = 0.0f;

    GEMM_MAINLOOP(Ab, Bb, sbase, acc)

    const int g = lane >> 2, t2 = (lane & 3) * 2;
    #pragma unroll
    for (int mt = 0; mt < 4; mt++) {
        #pragma unroll
        for (int hm = 0; hm < 2; hm++) {
            const int row_g = bm * 128 + wm * 64 + mt * 16 + hm * 8 + g;
            float* Crow = C + (size_t)row_g * D_MOD + bn * 128;
            #pragma unroll
            for (int nt = 0; nt < 4; nt++) {
                const int col = wn * 32 + nt * 8 + t2;
                float2 v;
                v.x = acc[mt][nt][hm * 2 + 0] + bias_s[col];
                v.y = acc[mt][nt][hm * 2 + 1] + bias_s[col + 1];
                *(float2*)(Crow + col) = v;
            }
        }
    }
}

// ---------------------------------------------------------------------------
// HMMA flash attention (causal). CTA = 128 queries of one (b,h), 256 thr / 8 warps.
// Warp owns 16 q-rows. Online softmax fp32; P reused from accumulators as
// fp16 A-fragments (no smem round trip). V via ldmatrix.x4.trans.
// smem: Q 16KB + 2 stages x (K 16KB + V 16KB) = 80KB.
// ---------------------------------------------------------------------------
__global__ __launch_bounds__(256, 1)
void attn_hmma_kernel(const __half* __restrict__ qh, const __half* __restrict__ kh,
                      const __half* __restrict__ vh, __half* __restrict__ ctxh)
{
    extern __shared__ char dsmem_raw[];
    uint32_t sbase = smem_u32(dsmem_raw);
    sbase = (sbase + 1023u) & ~1023u;
    const uint32_t Qsm = sbase;

    const int qt = (int)(gridDim.x - 1 - blockIdx.x);   // reversed: heavy CTAs first
    const int h  = blockIdx.y;
    const int b  = blockIdx.z;
    const int tid = threadIdx.x;
    const int lane = tid & 31;
    const int wid  = tid >> 5;
    const int m0   = wid * 16;

    const size_t bh_off = ((size_t)b * T_SEQ) * D_MOD + h * HDIM;
    const __half* Qg = qh + bh_off + (size_t)qt * 128 * D_MOD;
    const __half* Kg = kh + bh_off;
    const __half* Vg = vh + bh_off;

    // prologue: Q + (K,V) tile 0 in one group
    #pragma unroll
    for (int t = 0; t < 4; t++) {
        const int c = tid + t * 256;
        const int r = c >> 3, u = c & 7;
        cp16(Qsm + SWZ((uint32_t)(r * 128 + u * 16)), Qg + (size_t)r * D_MOD + u * 8);
    }
    {
        const uint32_t Kst = sbase + 16384u, Vst = Kst + 16384u;
        #pragma unroll
        for (int t = 0; t < 4; t++) {
            const int c = tid + t * 256;
            const int r = c >> 3, u = c & 7;
            cp16(Kst + SWZ((uint32_t)(r * 128 + u * 16)), Kg + (size_t)r * D_MOD + u * 8);
            cp16(Vst + SWZ((uint32_t)(r * 128 + u * 16)), Vg + (size_t)r * D_MOD + u * 8);
        }
        asm volatile("cp.async.commit_group;" ::: "memory");
    }

    const int lrow = lane & 15;
    const int lcol = (lane >> 4) * 16;

    uint32_t qf[4][4];
    float oacc[8][4];
    #pragma unroll
    for (int j = 0; j < 8; j++)
        #pragma unroll
        for (int q = 0; q < 4; q++) oacc[j][q] = 0.0f;
    float mrun0 = -1e30f, mrun1 = -1e30f, lrun0 = 0.0f, lrun1 = 0.0f;

    for (int i = 0; i <= qt; i++) {
        const int s = i & 1;
        if (i + 1 <= qt) {
            const uint32_t Kst = sbase + 16384u + (uint32_t)(s ^ 1) * 32768u;
            const uint32_t Vst = Kst + 16384u;
            const __half* Kn = Kg + (size_t)(i + 1) * 128 * D_MOD;
            const __half* Vn = Vg + (size_t)(i + 1) * 128 * D_MOD;
            #pragma unroll
            for (int t = 0; t < 4; t++) {
                const int c = tid + t * 256;
                const int r = c >> 3, u = c & 7;
                cp16(Kst + SWZ((uint32_t)(r * 128 + u * 16)), Kn + (size_t)r * D_MOD + u * 8);
                cp16(Vst + SWZ((uint32_t)(r * 128 + u * 16)), Vn + (size_t)r * D_MOD + u * 8);
            }
            asm volatile("cp.async.commit_group;" ::: "memory");
            asm volatile("cp.async.wait_group 1;" ::: "memory");
        } else {
            asm volatile("cp.async.wait_group 0;" ::: "memory");
        }
        __syncthreads();

        if (i == 0) {
            #pragma unroll
            for (int ks = 0; ks < 4; ks++)
                ldmx4(qf[ks], Qsm + SWZ((uint32_t)((m0 + lrow) * 128 + ks * 32 + lcol)));
        }

        const uint32_t Kst = sbase + 16384u + (uint32_t)s * 32768u;
        const uint32_t Vst = Kst + 16384u;

        // S = Q @ K^T : 16 q-rows x 128 keys per warp
        float sacc[16][4];
        #pragma unroll
        for (int nt = 0; nt < 16; nt++)
            #pragma unroll
            for (int q = 0; q < 4; q++) sacc[nt][q] = 0.0f;

        #pragma unroll
        for (int gblk = 0; gblk < 8; gblk++) {       // 16 keys per block
            #pragma unroll
            for (int ks = 0; ks < 4; ks++) {
                uint32_t kf[4];
                ldmx4(kf, Kst + SWZ((uint32_t)((gblk * 16 + lrow) * 128 + ks * 32 + lcol)));
                mma16816(sacc[gblk * 2 + 0], qf[ks], kf[0], kf[2]);
                mma16816(sacc[gblk * 2 + 1], qf[ks], kf[1], kf[3]);
            }
        }

        // causal mask on diagonal tile
        if (i == qt) {
            const int row0 = m0 + (lane >> 2);
            #pragma unroll
            for (int nt = 0; nt < 16; nt++) {
                const int cb = nt * 8 + (lane & 3) * 2;
                if (cb + 0 > row0) sacc[nt][0] = -1e30f;
                if (cb + 1 > row0) sacc[nt][1] = -1e30f;
                if (cb + 0 > row0 + 8) sacc[nt][2] = -1e30f;
                if (cb + 1 > row0 + 8) sacc[nt][3] = -1e30f;
            }
        }

        // online softmax (rows r = lane>>2 and r+8 of this warp's 16)
        float mx0 = -1e30f, mx1 = -1e30f;
        #pragma unroll
        for (int nt = 0; nt < 16; nt++) {
            mx0 = fmaxf(mx0, fmaxf(sacc[nt][0], sacc[nt][1]));
            mx1 = fmaxf(mx1, fmaxf(sacc[nt][2], sacc[nt][3]));
        }
        mx0 = fmaxf(mx0, __shfl_xor_sync(0xffffffffu, mx0, 1));
        mx0 = fmaxf(mx0, __shfl_xor_sync(0xffffffffu, mx0, 2));
        mx1 = fmaxf(mx1, __shfl_xor_sync(0xffffffffu, mx1, 1));
        mx1 = fmaxf(mx1, __shfl_xor_sync(0xffffffffu, mx1, 2));

        const float mnew0 = fmaxf(mrun0, mx0);
        const float mnew1 = fmaxf(mrun1, mx1);
        const float alpha0 = __expf(mrun0 - mnew0);
        const float alpha1 = __expf(mrun1 - mnew1);

        float sum0 = 0.0f, sum1 = 0.0f;
        #pragma unroll
        for (int nt = 0; nt < 16; nt++) {
            sacc[nt][0] = __expf(sacc[nt][0] - mnew0);
            sacc[nt][1] = __expf(sacc[nt][1] - mnew0);
            sacc[nt][2] = __expf(sacc[nt][2] - mnew1);
            sacc[nt][3] = __expf(sacc[nt][3] - mnew1);
            sum0 += sacc[nt][0] + sacc[nt][1];
            sum1 += sacc[nt][2] + sacc[nt][3];
        }
        sum0 += __shfl_xor_sync(0xffffffffu, sum0, 1);
        sum0 += __shfl_xor_sync(0xffffffffu, sum0, 2);
        sum1 += __shfl_xor_sync(0xffffffffu, sum1, 1);
        sum1 += __shfl_xor_sync(0xffffffffu, sum1, 2);

        lrun0 = lrun0 * alpha0 + sum0;
        lrun1 = lrun1 * alpha1 + sum1;
        mrun0 = mnew0; mrun1 = mnew1;

        #pragma unroll
        for (int j = 0; j < 8; j++) {
            oacc[j][0] *= alpha0; oacc[j][1] *= alpha0;
            oacc[j][2] *= alpha1; oacc[j][3] *= alpha1;
        }

        // O += P @ V  (P from sacc accumulators, V via ldmatrix trans)
        #pragma unroll
        for (int ksv = 0; ksv < 8; ksv++) {          // 16 keys per step
            uint32_t paf[4];
            __half2 h0 = __floats2half2_rn(sacc[2 * ksv][0], sacc[2 * ksv][1]);
            __half2 h1 = __floats2half2_rn(sacc[2 * ksv][2], sacc[2 * ksv][3]);
            __half2 h2 = __floats2half2_rn(sacc[2 * ksv + 1][0], sacc[2 * ksv + 1][1]);
            __half2 h3 = __floats2half2_rn(sacc[2 * ksv + 1][2], sacc[2 * ksv + 1][3]);
            paf[0] = *(uint32_t*)&h0;
            paf[1] = *(uint32_t*)&h1;
            paf[2] = *(uint32_t*)&h2;
            paf[3] = *(uint32_t*)&h3;
            #pragma unroll
            for (int j = 0; j < 4; j++) {            // 16 hd cols per trans load
                uint32_t vf[4];
                ldmx4t(vf, Vst + SWZ((uint32_t)((ksv * 16 + lrow) * 128 + j * 32 + lcol)));
                mma16816(oacc[2 * j + 0], paf, vf[0], vf[1]);
                mma16816(oacc[2 * j + 1], paf, vf[2], vf[3]);
            }
        }
        __syncthreads();
    }

    // epilogue: normalize, write ctx fp16 (merged layout)
    const float inv0 = 1.0f / lrun0;
    const float inv1 = 1.0f / lrun1;
    const int r0 = qt * 128 + m0 + (lane >> 2);
    __half* C0 = ctxh + ((size_t)b * T_SEQ + r0) * D_MOD + h * HDIM + (lane & 3) * 2;
    __half* C1 = C0 + 8ull * D_MOD;
    #pragma unroll
    for (int j = 0; j < 8; j++) {
        *(__half2*)(C0 + j * 8) = __floats2half2_rn(oacc[j][0] * inv0, oacc[j][1] * inv0);
        *(__half2*)(C1 + j * 8) = __floats2half2_rn(oacc[j][2] * inv1, oacc[j][3] * inv1);
    }
}

// ---------------------------------------------------------------------------
// Launch
// ---------------------------------------------------------------------------
extern "C" void kernel_launch(void* const* d_in, const int* in_sizes, int n_in,
                              void* d_out, int out_size)
{
    const float* x  = (const float*)d_in[0];
    const float* Wq = (const float*)d_in[4];
    const float* bq = (const float*)d_in[5];
    const float* Wk = (const float*)d_in[6];
    const float* bk = (const float*)d_in[7];
    const float* Wv = (const float*)d_in[8];
    const float* bv = (const float*)d_in[9];
    const float* Wo = (const float*)d_in[10];
    const float* bo = (const float*)d_in[11];

    float* out = (float*)d_out;
    float* cache_out = out + (size_t)M_ROWS * D_MOD;

    __half *xh, *wh, *qh, *kh, *vh, *ctxh;
    cudaGetSymbolAddress((void**)&xh, g_xh);
    cudaGetSymbolAddress((void**)&wh, g_wh);
    cudaGetSymbolAddress((void**)&qh, g_qh);
    cudaGetSymbolAddress((void**)&kh, g_kh);
    cudaGetSymbolAddress((void**)&vh, g_vh);
    cudaGetSymbolAddress((void**)&ctxh, g_ctxh);

    const int smem_gemm = STAGES * STAGE_BYTES + 1024;          // 99 KB
    const int smem_attn = 16384 + 2 * 32768 + 1024;             // 82 KB
    cudaFuncSetAttribute(gemm_qkv_kernel, cudaFuncAttributeMaxDynamicSharedMemorySize, smem_gemm);
    cudaFuncSetAttribute(gemm_out_kernel, cudaFuncAttributeMaxDynamicSharedMemorySize, smem_gemm);
    cudaFuncSetAttribute(attn_hmma_kernel, cudaFuncAttributeMaxDynamicSharedMemorySize, smem_attn);

    const size_t WSZ = (size_t)D_MOD * D_MOD;

    // 1) prep
    convert_x_kernel<<<(M_ROWS * D_MOD) / (256 * 4), 256>>>(x, xh);
    dim3 tgrid(D_MOD / 32, D_MOD / 32, 4);
    convert_wt_kernel<<<tgrid, 256>>>(Wq, Wk, Wv, Wo, wh);

    // 2) fused QKV projection
    dim3 qkvgrid(48, 32);
    gemm_qkv_kernel<<<qkvgrid, 256, smem_gemm>>>(xh, wh, bq, bk, bv,
                                                 cache_out, qh, kh, vh);

    // 3) HMMA causal flash attention
    dim3 agrid(T_SEQ / 128, NHEAD, BATCH);   // (8, 32, 4)
    attn_hmma_kernel<<<agrid, 256, smem_attn>>>(qh, kh, vh, ctxh);

    // 4) output projection
    dim3 ogrid(16, 32);
    gemm_out_kernel<<<ogrid, 256, smem_gemm>>>(ctxh, wh + 3 * WSZ, bo, out);
}

// round 7
// speedup vs baseline: 8.0051x; 1.0040x over previous
#include <cuda_runtime.h>
#include <cuda_fp16.h>
#include <cstdint>

// Problem constants
#define BATCH 4
#define T_SEQ 1024
#define D_MOD 2048
#define NHEAD 32
#define HDIM  64
#define M_ROWS (BATCH * T_SEQ)      // 4096

#define STAGES 3
#define BK 64                       // fp16 K-slab (128 bytes per row)
#define NSLAB (D_MOD / BK)          // 32
#define STAGE_BYTES 32768           // (128*64 + 128*64) * 2
#define TNLL ((long long)T_SEQ * D_MOD)

// Scratch (device globals; allocation-free per harness rules)
__device__ __half g_xh[(size_t)M_ROWS * D_MOD];          // x fp16 [M][K]
__device__ __half g_wh[4ull * D_MOD * D_MOD];            // weights fp16 [N][K] x4 (q,k,v,o)
__device__ __half g_qh[(size_t)M_ROWS * D_MOD];          // Q*scale*log2e fp16
__device__ __half g_kh[(size_t)M_ROWS * D_MOD];          // K fp16
__device__ __half g_vh[(size_t)M_ROWS * D_MOD];          // V fp16
__device__ __half g_ctxh[(size_t)M_ROWS * D_MOD];        // attn ctx fp16

// ---------------------------------------------------------------------------
// helpers
// ---------------------------------------------------------------------------
__device__ __forceinline__ uint32_t smem_u32(const void* p) {
    return (uint32_t)__cvta_generic_to_shared(p);
}
#define SWZ(o) ((o) ^ (((o) >> 3) & 0x70))

__device__ __forceinline__ void cp16(uint32_t dst, const void* src) {
    asm volatile("cp.async.cg.shared.global [%0], [%1], 16;" :: "r"(dst), "l"(src));
}
__device__ __forceinline__ void ldmx4(uint32_t* r, uint32_t addr) {
    asm volatile("ldmatrix.sync.aligned.m8n8.x4.shared.b16 {%0,%1,%2,%3}, [%4];"
                 : "=r"(r[0]), "=r"(r[1]), "=r"(r[2]), "=r"(r[3]) : "r"(addr));
}
__device__ __forceinline__ void ldmx4t(uint32_t* r, uint32_t addr) {
    asm volatile("ldmatrix.sync.aligned.m8n8.x4.trans.shared.b16 {%0,%1,%2,%3}, [%4];"
                 : "=r"(r[0]), "=r"(r[1]), "=r"(r[2]), "=r"(r[3]) : "r"(addr));
}
__device__ __forceinline__ void mma16816(float* c, const uint32_t* a,
                                         uint32_t b0, uint32_t b1) {
    asm volatile(
        "mma.sync.aligned.m16n8k16.row.col.f32.f16.f16.f32 "
        "{%0,%1,%2,%3}, {%4,%5,%6,%7}, {%8,%9}, {%0,%1,%2,%3};"
        : "+f"(c[0]), "+f"(c[1]), "+f"(c[2]), "+f"(c[3])
        : "r"(a[0]), "r"(a[1]), "r"(a[2]), "r"(a[3]), "r"(b0), "r"(b1));
}
// fp16x2 exp2 on the MUFU pipe: 2 exponentials per MUFU op
__device__ __forceinline__ uint32_t ex2_f16x2(uint32_t x) {
    uint32_t r;
    asm volatile("ex2.approx.f16x2 %0, %1;" : "=r"(r) : "r"(x));
    return r;
}

// ---------------------------------------------------------------------------
// Prep: x (f32) -> fp16
// ---------------------------------------------------------------------------
__global__ __launch_bounds__(256)
void convert_x_kernel(const float* __restrict__ x, __half* __restrict__ xh)
{
    const size_t i = (size_t)blockIdx.x * 256 + threadIdx.x;
    float4 v = ((const float4*)x)[i];
    __half2* o = (__half2*)xh;
    o[i * 2 + 0] = __floats2half2_rn(v.x, v.y);
    o[i * 2 + 1] = __floats2half2_rn(v.z, v.w);
}

// ---------------------------------------------------------------------------
// Prep: W [K][N] f32 -> Wh [N][K] fp16 (transpose + convert), 4 matrices
// ---------------------------------------------------------------------------
__global__ __launch_bounds__(256)
void convert_wt_kernel(const float* __restrict__ w0, const float* __restrict__ w1,
                       const float* __restrict__ w2, const float* __restrict__ w3,
                       __half* __restrict__ dst)
{
    __shared__ float tile[32][33];
    const float* src = blockIdx.z == 0 ? w0 : blockIdx.z == 1 ? w1
                     : blockIdx.z == 2 ? w2 : w3;
    __half* d = dst + (size_t)blockIdx.z * D_MOD * D_MOD;
    const int tx = threadIdx.x & 31, ty = threadIdx.x >> 5;
    const int n0 = blockIdx.x * 32, k0 = blockIdx.y * 32;
    #pragma unroll
    for (int r = 0; r < 32; r += 8)
        tile[ty + r][tx] = src[(size_t)(k0 + ty + r) * D_MOD + n0 + tx];
    __syncthreads();
    #pragma unroll
    for (int r = 0; r < 32; r += 8)
        d[(size_t)(n0 + ty + r) * D_MOD + k0 + tx] = __float2half(tile[tx][ty + r]);
}

// ---------------------------------------------------------------------------
// GEMM mainloop: 3-stage cp.async pipeline, one __syncthreads per iteration.
// ---------------------------------------------------------------------------
#define GEMM_MAINLOOP(Ab, Bb, sbase, acc)                                       \
    {                                                                           \
        _Pragma("unroll")                                                       \
        for (int s = 0; s < STAGES - 1; s++) {                                  \
            const uint32_t stA = sbase + s * STAGE_BYTES;                       \
            const uint32_t stB = stA + 16384u;                                  \
            const int kb = s * BK;                                              \
            _Pragma("unroll")                                                   \
            for (int t = 0; t < 4; t++) {                                       \
                const int c = tid + t * 256;                                    \
                const int r = c >> 3, u = c & 7;                                \
                cp16(stA + SWZ((uint32_t)(r * 128 + u * 16)), Ab + (size_t)r * D_MOD + kb + u * 8); \
                cp16(stB + SWZ((uint32_t)(r * 128 + u * 16)), Bb + (size_t)r * D_MOD + kb + u * 8); \
            }                                                                   \
            asm volatile("cp.async.commit_group;" ::: "memory");                \
        }                                                                       \
        const int lrow = lane & 15;                                             \
        const int lcol = (lane >> 4) * 16;                                      \
        int sc = 0, sl = STAGES - 1;                                            \
        for (int i = 0; i < NSLAB; i++) {                                       \
            asm volatile("cp.async.wait_group %0;" :: "n"(STAGES - 2) : "memory"); \
            __syncthreads();                                                    \
            if (i + STAGES - 1 < NSLAB) {                                       \
                const uint32_t stA = sbase + sl * STAGE_BYTES;                  \
                const uint32_t stB = stA + 16384u;                              \
                const int kb = (i + STAGES - 1) * BK;                           \
                _Pragma("unroll")                                               \
                for (int t = 0; t < 4; t++) {                                   \
                    const int c = tid + t * 256;                                \
                    const int r = c >> 3, u = c & 7;                            \
                    cp16(stA + SWZ((uint32_t)(r * 128 + u * 16)), Ab + (size_t)r * D_MOD + kb + u * 8); \
                    cp16(stB + SWZ((uint32_t)(r * 128 + u * 16)), Bb + (size_t)r * D_MOD + kb + u * 8); \
                }                                                               \
            }                                                                   \
            asm volatile("cp.async.commit_group;" ::: "memory");                \
            sl = (sl + 1 == STAGES) ? 0 : sl + 1;                               \
            const uint32_t stA = sbase + sc * STAGE_BYTES;                      \
            const uint32_t stB = stA + 16384u;                                  \
            sc = (sc + 1 == STAGES) ? 0 : sc + 1;                               \
            _Pragma("unroll")                                                   \
            for (int ks = 0; ks < BK / 16; ks++) {                              \
                uint32_t afr[4][4], bfr[2][4];                                  \
                _Pragma("unroll")                                               \
                for (int mt = 0; mt < 4; mt++)                                  \
                    ldmx4(afr[mt], stA + SWZ((uint32_t)((wm * 64 + mt * 16 + lrow) * 128 + ks * 32 + lcol))); \
                _Pragma("unroll")                                               \
                for (int bt = 0; bt < 2; bt++)                                  \
                    ldmx4(bfr[bt], stB + SWZ((uint32_t)((wn * 32 + bt * 16 + lrow) * 128 + ks * 32 + lcol))); \
                _Pragma("unroll")                                               \
                for (int mt = 0; mt < 4; mt++)                                  \
                    _Pragma("unroll")                                           \
                    for (int nt = 0; nt < 4; nt++) {                            \
                        const int bt = nt >> 1, sub = nt & 1;                   \
                        mma16816(acc[mt][nt], afr[mt], bfr[bt][sub], bfr[bt][sub + 2]); \
                    }                                                           \
            }                                                                   \
        }                                                                       \
    }

// ---------------------------------------------------------------------------
// Fused QKV projection GEMM. grid = (48, 32). bn segment: 0-15 Q, 16-31 K, 32-47 V.
// Q -> g_qh fp16 (scaled by 0.125*log2e for exp2-domain softmax).
// K/V -> cache f32 (remapped) + fp16 copies.
// ---------------------------------------------------------------------------
__global__ __launch_bounds__(256, 2)
void gemm_qkv_kernel(const __half* __restrict__ A, const __half* __restrict__ B,
                     const float* __restrict__ bq, const float* __restrict__ bk,
                     const float* __restrict__ bv, float* __restrict__ cache,
                     __half* __restrict__ qh, __half* __restrict__ kh,
                     __half* __restrict__ vh)
{
    extern __shared__ char dsmem_raw[];
    __shared__ float bias_s[128];

    const int tid  = threadIdx.x;
    const int lane = tid & 31;
    const int wid  = tid >> 5;
    const int wm   = wid & 1;
    const int wn   = wid >> 1;
    const int bm = blockIdx.y, bn = blockIdx.x;
    const int seg = bn >> 4;           // 0=q 1=k 2=v
    const int bnn = bn & 15;

    uint32_t sbase = smem_u32(dsmem_raw);
    sbase = (sbase + 1023u) & ~1023u;

    const float* bp = seg == 0 ? bq : seg == 1 ? bk : bv;
    if (tid < 128) bias_s[tid] = bp[bnn * 128 + tid];

    const __half* Ab = A + (size_t)bm * 128 * D_MOD;
    const __half* Bb = B + (size_t)bn * 128 * D_MOD;

    float acc[4][4][4];
    #pragma unroll
    for (int i = 0; i < 4; i++)
        #pragma unroll
        for (int j = 0; j < 4; j++)
            #pragma unroll
            for (int q = 0; q < 4; q++) acc[i][j][q] = 0.0f;

    GEMM_MAINLOOP(Ab, Bb, sbase, acc)

    __half* hout = seg == 0 ? qh : seg == 1 ? kh : vh;
    // Q scale: HD^-0.5 * log2(e) so attention softmax runs in exp2 domain
    const float hscale = seg == 0 ? 0.18033688f : 1.0f;

    const int g = lane >> 2, t2 = (lane & 3) * 2;
    #pragma unroll
    for (int mt = 0; mt < 4; mt++) {
        #pragma unroll
        for (int hm = 0; hm < 2; hm++) {
            const int row_g = bm * 128 + wm * 64 + mt * 16 + hm * 8 + g;
            __half* Hrow = hout + (size_t)row_g * D_MOD + bnn * 128;
            float* Crow = nullptr;
            if (seg) {
                const int bb = row_g >> 10, tt = row_g & 1023;
                Crow = cache + (long long)bb * 2 * TNLL + (seg == 2 ? TNLL : 0)
                             + (long long)tt * D_MOD + bnn * 128;
            }
            #pragma unroll
            for (int nt = 0; nt < 4; nt++) {
                const int col = wn * 32 + nt * 8 + t2;
                float2 v;
                v.x = acc[mt][nt][hm * 2 + 0] + bias_s[col];
                v.y = acc[mt][nt][hm * 2 + 1] + bias_s[col + 1];
                *(__half2*)(Hrow + col) = __floats2half2_rn(v.x * hscale, v.y * hscale);
                if (seg) *(float2*)(Crow + col) = v;
            }
        }
    }
}

// ---------------------------------------------------------------------------
// Output projection GEMM: out(f32) = ctxh @ WoT^T + bo. grid = (16, 32).
// ---------------------------------------------------------------------------
__global__ __launch_bounds__(256, 2)
void gemm_out_kernel(const __half* __restrict__ A, const __half* __restrict__ B,
                     const float* __restrict__ bias, float* __restrict__ C)
{
    extern __shared__ char dsmem_raw[];
    __shared__ float bias_s[128];

    const int tid  = threadIdx.x;
    const int lane = tid & 31;
    const int wid  = tid >> 5;
    const int wm   = wid & 1;
    const int wn   = wid >> 1;
    const int bm = blockIdx.y, bn = blockIdx.x;

    uint32_t sbase = smem_u32(dsmem_raw);
    sbase = (sbase + 1023u) & ~1023u;

    if (tid < 128) bias_s[tid] = bias[bn * 128 + tid];

    const __half* Ab = A + (size_t)bm * 128 * D_MOD;
    const __half* Bb = B + (size_t)bn * 128 * D_MOD;

    float acc[4][4][4];
    #pragma unroll
    for (int i = 0; i < 4; i++)
        #pragma unroll
        for (int j = 0; j < 4; j++)
            #pragma unroll
            for (int q = 0; q < 4; q++) acc[i][j][q] = 0.0f;

    GEMM_MAINLOOP(Ab, Bb, sbase, acc)

    const int g = lane >> 2, t2 = (lane & 3) * 2;
    #pragma unroll
    for (int mt = 0; mt < 4; mt++) {
        #pragma unroll
        for (int hm = 0; hm < 2; hm++) {
            const int row_g = bm * 128 + wm * 64 + mt * 16 + hm * 8 + g;
            float* Crow = C + (size_t)row_g * D_MOD + bn * 128;
            #pragma unroll
            for (int nt = 0; nt < 4; nt++) {
                const int col = wn * 32 + nt * 8 + t2;
                float2 v;
                v.x = acc[mt][nt][hm * 2 + 0] + bias_s[col];
                v.y = acc[mt][nt][hm * 2 + 1] + bias_s[col + 1];
                *(float2*)(Crow + col) = v;
            }
        }
    }
}

// ---------------------------------------------------------------------------
// HMMA flash attention (causal, exp2 domain). CTA = 128 queries of one (b,h).
// 256 thr / 8 warps, warp owns 16 q-rows. Softmax exponentials computed as
// fp16x2 ex2 (half the MUFU ops); the exp results ARE the PV A-fragments.
// smem: Q 16KB + 2 stages x (K 16KB + V 16KB) = 80KB.
// ---------------------------------------------------------------------------
__global__ __launch_bounds__(256, 1)
void attn_hmma_kernel(const __half* __restrict__ qh, const __half* __restrict__ kh,
                      const __half* __restrict__ vh, __half* __restrict__ ctxh)
{
    extern __shared__ char dsmem_raw[];
    uint32_t sbase = smem_u32(dsmem_raw);
    sbase = (sbase + 1023u) & ~1023u;
    const uint32_t Qsm = sbase;

    const int qt = (int)(gridDim.x - 1 - blockIdx.x);   // reversed: heavy CTAs first
    const int h  = blockIdx.y;
    const int b  = blockIdx.z;
    const int tid = threadIdx.x;
    const int lane = tid & 31;
    const int wid  = tid >> 5;
    const int m0   = wid * 16;

    const size_t bh_off = ((size_t)b * T_SEQ) * D_MOD + h * HDIM;
    const __half* Qg = qh + bh_off + (size_t)qt * 128 * D_MOD;
    const __half* Kg = kh + bh_off;
    const __half* Vg = vh + bh_off;

    // prologue: Q + (K,V) tile 0 in one group
    #pragma unroll
    for (int t = 0; t < 4; t++) {
        const int c = tid + t * 256;
        const int r = c >> 3, u = c & 7;
        cp16(Qsm + SWZ((uint32_t)(r * 128 + u * 16)), Qg + (size_t)r * D_MOD + u * 8);
    }
    {
        const uint32_t Kst = sbase + 16384u, Vst = Kst + 16384u;
        #pragma unroll
        for (int t = 0; t < 4; t++) {
            const int c = tid + t * 256;
            const int r = c >> 3, u = c & 7;
            cp16(Kst + SWZ((uint32_t)(r * 128 + u * 16)), Kg + (size_t)r * D_MOD + u * 8);
            cp16(Vst + SWZ((uint32_t)(r * 128 + u * 16)), Vg + (size_t)r * D_MOD + u * 8);
        }
        asm volatile("cp.async.commit_group;" ::: "memory");
    }

    const int lrow = lane & 15;
    const int lcol = (lane >> 4) * 16;

    uint32_t qf[4][4];
    float oacc[8][4];
    #pragma unroll
    for (int j = 0; j < 8; j++)
        #pragma unroll
        for (int q = 0; q < 4; q++) oacc[j][q] = 0.0f;
    float mrun0 = -1e30f, mrun1 = -1e30f, lrun0 = 0.0f, lrun1 = 0.0f;

    for (int i = 0; i <= qt; i++) {
        const int s = i & 1;
        if (i + 1 <= qt) {
            const uint32_t Kst = sbase + 16384u + (uint32_t)(s ^ 1) * 32768u;
            const uint32_t Vst = Kst + 16384u;
            const __half* Kn = Kg + (size_t)(i + 1) * 128 * D_MOD;
            const __half* Vn = Vg + (size_t)(i + 1) * 128 * D_MOD;
            #pragma unroll
            for (int t = 0; t < 4; t++) {
                const int c = tid + t * 256;
                const int r = c >> 3, u = c & 7;
                cp16(Kst + SWZ((uint32_t)(r * 128 + u * 16)), Kn + (size_t)r * D_MOD + u * 8);
                cp16(Vst + SWZ((uint32_t)(r * 128 + u * 16)), Vn + (size_t)r * D_MOD + u * 8);
            }
            asm volatile("cp.async.commit_group;" ::: "memory");
            asm volatile("cp.async.wait_group 1;" ::: "memory");
        } else {
            asm volatile("cp.async.wait_group 0;" ::: "memory");
        }
        __syncthreads();   // also orders: prior-iter compute done before these loads land

        if (i == 0) {
            #pragma unroll
            for (int ks = 0; ks < 4; ks++)
                ldmx4(qf[ks], Qsm + SWZ((uint32_t)((m0 + lrow) * 128 + ks * 32 + lcol)));
        }

        const uint32_t Kst = sbase + 16384u + (uint32_t)s * 32768u;
        const uint32_t Vst = Kst + 16384u;

        // S = Q @ K^T : 16 q-rows x 128 keys per warp (exp2-domain logits)
        float sacc[16][4];
        #pragma unroll
        for (int nt = 0; nt < 16; nt++)
            #pragma unroll
            for (int q = 0; q < 4; q++) sacc[nt][q] = 0.0f;

        #pragma unroll
        for (int gblk = 0; gblk < 8; gblk++) {       // 16 keys per block
            #pragma unroll
            for (int ks = 0; ks < 4; ks++) {
                uint32_t kf[4];
                ldmx4(kf, Kst + SWZ((uint32_t)((gblk * 16 + lrow) * 128 + ks * 32 + lcol)));
                mma16816(sacc[gblk * 2 + 0], qf[ks], kf[0], kf[2]);
                mma16816(sacc[gblk * 2 + 1], qf[ks], kf[1], kf[3]);
            }
        }

        // causal mask on diagonal tile
        if (i == qt) {
            const int row0 = m0 + (lane >> 2);
            #pragma unroll
            for (int nt = 0; nt < 16; nt++) {
                const int cb = nt * 8 + (lane & 3) * 2;
                if (cb + 0 > row0) sacc[nt][0] = -1e30f;
                if (cb + 1 > row0) sacc[nt][1] = -1e30f;
                if (cb + 0 > row0 + 8) sacc[nt][2] = -1e30f;
                if (cb + 1 > row0 + 8) sacc[nt][3] = -1e30f;
            }
        }

        // online softmax (rows r = lane>>2 and r+8); P = exp2(s - mnew) in fp16x2
        float mx0 = -1e30f, mx1 = -1e30f;
        #pragma unroll
        for (int nt = 0; nt < 16; nt++) {
            mx0 = fmaxf(mx0, fmaxf(sacc[nt][0], sacc[nt][1]));
            mx1 = fmaxf(mx1, fmaxf(sacc[nt][2], sacc[nt][3]));
        }
        mx0 = fmaxf(mx0, __shfl_xor_sync(0xffffffffu, mx0, 1));
        mx0 = fmaxf(mx0, __shfl_xor_sync(0xffffffffu, mx0, 2));
        mx1 = fmaxf(mx1, __shfl_xor_sync(0xffffffffu, mx1, 1));
        mx1 = fmaxf(mx1, __shfl_xor_sync(0xffffffffu, mx1, 2));

        const float mnew0 = fmaxf(mrun0, mx0);
        const float mnew1 = fmaxf(mrun1, mx1);
        const float alpha0 = exp2f(mrun0 - mnew0);
        const float alpha1 = exp2f(mrun1 - mnew1);

        uint32_t pf0[16], pf1[16];   // fp16x2 P: rows r / r+8, cols nt*8+{t2,t2+1}
        float sum0 = 0.0f, sum1 = 0.0f;
        #pragma unroll
        for (int nt = 0; nt < 16; nt++) {
            __half2 d0 = __floats2half2_rn(sacc[nt][0] - mnew0, sacc[nt][1] - mnew0);
            __half2 d1 = __floats2half2_rn(sacc[nt][2] - mnew1, sacc[nt][3] - mnew1);
            pf0[nt] = ex2_f16x2(*(uint32_t*)&d0);
            pf1[nt] = ex2_f16x2(*(uint32_t*)&d1);
            const float2 e0 = __half22float2(*(__half2*)&pf0[nt]);
            const float2 e1 = __half22float2(*(__half2*)&pf1[nt]);
            sum0 += e0.x + e0.y;
            sum1 += e1.x + e1.y;
        }
        sum0 += __shfl_xor_sync(0xffffffffu, sum0, 1);
        sum0 += __shfl_xor_sync(0xffffffffu, sum0, 2);
        sum1 += __shfl_xor_sync(0xffffffffu, sum1, 1);
        sum1 += __shfl_xor_sync(0xffffffffu, sum1, 2);

        lrun0 = lrun0 * alpha0 + sum0;
        lrun1 = lrun1 * alpha1 + sum1;
        mrun0 = mnew0; mrun1 = mnew1;

        #pragma unroll
        for (int j = 0; j < 8; j++) {
            oacc[j][0] *= alpha0; oacc[j][1] *= alpha0;
            oacc[j][2] *= alpha1; oacc[j][3] *= alpha1;
        }

        // O += P @ V  (P fragments directly from pf arrays)
        #pragma unroll
        for (int ksv = 0; ksv < 8; ksv++) {          // 16 keys per step
            uint32_t paf[4];
            paf[0] = pf0[2 * ksv];
            paf[1] = pf1[2 * ksv];
            paf[2] = pf0[2 * ksv + 1];
            paf[3] = pf1[2 * ksv + 1];
            #pragma unroll
            for (int j = 0; j < 4; j++) {            // 16 hd cols per trans load
                uint32_t vf[4];
                ldmx4t(vf, Vst + SWZ((uint32_t)((ksv * 16 + lrow) * 128 + j * 32 + lcol)));
                mma16816(oacc[2 * j + 0], paf, vf[0], vf[1]);
                mma16816(oacc[2 * j + 1], paf, vf[2], vf[3]);
            }
        }
        // no trailing sync: next iteration's top barrier orders smem reuse
    }

    // epilogue: normalize, write ctx fp16 (merged layout)
    const float inv0 = 1.0f / lrun0;
    const float inv1 = 1.0f / lrun1;
    const int r0 = qt * 128 + m0 + (lane >> 2);
    __half* C0 = ctxh + ((size_t)b * T_SEQ + r0) * D_MOD + h * HDIM + (lane & 3) * 2;
    __half* C1 = C0 + 8ull * D_MOD;
    #pragma unroll
    for (int j = 0; j < 8; j++) {
        *(__half2*)(C0 + j * 8) = __floats2half2_rn(oacc[j][0] * inv0, oacc[j][1] * inv0);
        *(__half2*)(C1 + j * 8) = __floats2half2_rn(oacc[j][2] * inv1, oacc[j][3] * inv1);
    }
}

// ---------------------------------------------------------------------------
// Launch
// ---------------------------------------------------------------------------
extern "C" void kernel_launch(void* const* d_in, const int* in_sizes, int n_in,
                              void* d_out, int out_size)
{
    const float* x  = (const float*)d_in[0];
    const float* Wq = (const float*)d_in[4];
    const float* bq = (const float*)d_in[5];
    const float* Wk = (const float*)d_in[6];
    const float* bk = (const float*)d_in[7];
    const float* Wv = (const float*)d_in[8];
    const float* bv = (const float*)d_in[9];
    const float* Wo = (const float*)d_in[10];
    const float* bo = (const float*)d_in[11];

    float* out = (float*)d_out;
    float* cache_out = out + (size_t)M_ROWS * D_MOD;

    __half *xh, *wh, *qh, *kh, *vh, *ctxh;
    cudaGetSymbolAddress((void**)&xh, g_xh);
    cudaGetSymbolAddress((void**)&wh, g_wh);
    cudaGetSymbolAddress((void**)&qh, g_qh);
    cudaGetSymbolAddress((void**)&kh, g_kh);
    cudaGetSymbolAddress((void**)&vh, g_vh);
    cudaGetSymbolAddress((void**)&ctxh, g_ctxh);

    const int smem_gemm = STAGES * STAGE_BYTES + 1024;          // 99 KB
    const int smem_attn = 16384 + 2 * 32768 + 1024;             // 82 KB
    cudaFuncSetAttribute(gemm_qkv_kernel, cudaFuncAttributeMaxDynamicSharedMemorySize, smem_gemm);
    cudaFuncSetAttribute(gemm_out_kernel, cudaFuncAttributeMaxDynamicSharedMemorySize, smem_gemm);
    cudaFuncSetAttribute(attn_hmma_kernel, cudaFuncAttributeMaxDynamicSharedMemorySize, smem_attn);

    const size_t WSZ = (size_t)D_MOD * D_MOD;

    // 1) prep
    convert_x_kernel<<<(M_ROWS * D_MOD) / (256 * 4), 256>>>(x, xh);
    dim3 tgrid(D_MOD / 32, D_MOD / 32, 4);
    convert_wt_kernel<<<tgrid, 256>>>(Wq, Wk, Wv, Wo, wh);

    // 2) fused QKV projection
    dim3 qkvgrid(48, 32);
    gemm_qkv_kernel<<<qkvgrid, 256, smem_gemm>>>(xh, wh, bq, bk, bv,
                                                 cache_out, qh, kh, vh);

    // 3) HMMA causal flash attention
    dim3 agrid(T_SEQ / 128, NHEAD, BATCH);   // (8, 32, 4)
    attn_hmma_kernel<<<agrid, 256, smem_attn>>>(qh, kh, vh, ctxh);

    // 4) output projection
    dim3 ogrid(16, 32);
    gemm_out_kernel<<<ogrid, 256, smem_gemm>>>(ctxh, wh + 3 * WSZ, bo, out);
}

// round 8
// speedup vs baseline: 8.0313x; 1.0033x over previous
#include <cuda_runtime.h>
#include <cuda_fp16.h>
#include <cstdint>

// Problem constants
#define BATCH 4
#define T_SEQ 1024
#define D_MOD 2048
#define NHEAD 32
#define HDIM  64
#define M_ROWS (BATCH * T_SEQ)      // 4096

#define STAGES 3
#define BK 64                       // fp16 K-slab (128 bytes per row)
#define NSLAB (D_MOD / BK)          // 32
#define STAGE_BYTES 32768           // (128*64 + 128*64) * 2
#define TNLL ((long long)T_SEQ * D_MOD)

// Scratch (device globals; allocation-free per harness rules)
__device__ __half g_xh[(size_t)M_ROWS * D_MOD];          // x fp16 [M][K]
__device__ __half g_wh[4ull * D_MOD * D_MOD];            // weights fp16 [N][K] x4 (q,k,v,o)
__device__ __half g_qh[(size_t)M_ROWS * D_MOD];          // Q*scale*log2e fp16
__device__ __half g_kh[(size_t)M_ROWS * D_MOD];          // K fp16
__device__ __half g_vh[(size_t)M_ROWS * D_MOD];          // V fp16
__device__ __half g_ctxh[(size_t)M_ROWS * D_MOD];        // attn ctx fp16

// ---------------------------------------------------------------------------
// helpers
// ---------------------------------------------------------------------------
__device__ __forceinline__ uint32_t smem_u32(const void* p) {
    return (uint32_t)__cvta_generic_to_shared(p);
}
#define SWZ(o) ((o) ^ (((o) >> 3) & 0x70))

__device__ __forceinline__ void cp16(uint32_t dst, const void* src) {
    asm volatile("cp.async.cg.shared.global [%0], [%1], 16;" :: "r"(dst), "l"(src));
}
// ldmatrix: volatile (reads barrier-guarded smem; must not be hoisted)
__device__ __forceinline__ void ldmx4(uint32_t* r, uint32_t addr) {
    asm volatile("ldmatrix.sync.aligned.m8n8.x4.shared.b16 {%0,%1,%2,%3}, [%4];"
                 : "=r"(r[0]), "=r"(r[1]), "=r"(r[2]), "=r"(r[3]) : "r"(addr));
}
__device__ __forceinline__ void ldmx4t(uint32_t* r, uint32_t addr) {
    asm volatile("ldmatrix.sync.aligned.m8n8.x4.trans.shared.b16 {%0,%1,%2,%3}, [%4];"
                 : "=r"(r[0]), "=r"(r[1]), "=r"(r[2]), "=r"(r[3]) : "r"(addr));
}
// mma: NON-volatile — ordering by register dataflow only, lets ptxas
// software-pipeline HMMAs against subsequent ldmatrix loads (CUTLASS style)
__device__ __forceinline__ void mma16816(float* c, const uint32_t* a,
                                         uint32_t b0, uint32_t b1) {
    asm("mma.sync.aligned.m16n8k16.row.col.f32.f16.f16.f32 "
        "{%0,%1,%2,%3}, {%4,%5,%6,%7}, {%8,%9}, {%0,%1,%2,%3};"
        : "+f"(c[0]), "+f"(c[1]), "+f"(c[2]), "+f"(c[3])
        : "r"(a[0]), "r"(a[1]), "r"(a[2]), "r"(a[3]), "r"(b0), "r"(b1));
}
// fp16x2 exp2 on the MUFU pipe: pure function, non-volatile
__device__ __forceinline__ uint32_t ex2_f16x2(uint32_t x) {
    uint32_t r;
    asm("ex2.approx.f16x2 %0, %1;" : "=r"(r) : "r"(x));
    return r;
}

// ---------------------------------------------------------------------------
// Prep: x (f32) -> fp16
// ---------------------------------------------------------------------------
__global__ __launch_bounds__(256)
void convert_x_kernel(const float* __restrict__ x, __half* __restrict__ xh)
{
    const size_t i = (size_t)blockIdx.x * 256 + threadIdx.x;
    float4 v = ((const float4*)x)[i];
    __half2* o = (__half2*)xh;
    o[i * 2 + 0] = __floats2half2_rn(v.x, v.y);
    o[i * 2 + 1] = __floats2half2_rn(v.z, v.w);
}

// ---------------------------------------------------------------------------
// Prep: W [K][N] f32 -> Wh [N][K] fp16 (transpose + convert), 4 matrices
// ---------------------------------------------------------------------------
__global__ __launch_bounds__(256)
void convert_wt_kernel(const float* __restrict__ w0, const float* __restrict__ w1,
                       const float* __restrict__ w2, const float* __restrict__ w3,
                       __half* __restrict__ dst)
{
    __shared__ float tile[32][33];
    const float* src = blockIdx.z == 0 ? w0 : blockIdx.z == 1 ? w1
                     : blockIdx.z == 2 ? w2 : w3;
    __half* d = dst + (size_t)blockIdx.z * D_MOD * D_MOD;
    const int tx = threadIdx.x & 31, ty = threadIdx.x >> 5;
    const int n0 = blockIdx.x * 32, k0 = blockIdx.y * 32;
    #pragma unroll
    for (int r = 0; r < 32; r += 8)
        tile[ty + r][tx] = src[(size_t)(k0 + ty + r) * D_MOD + n0 + tx];
    __syncthreads();
    #pragma unroll
    for (int r = 0; r < 32; r += 8)
        d[(size_t)(n0 + ty + r) * D_MOD + k0 + tx] = __float2half(tile[tx][ty + r]);
}

// ---------------------------------------------------------------------------
// GEMM mainloop: 3-stage cp.async pipeline, one __syncthreads per iteration.
// ---------------------------------------------------------------------------
#define GEMM_MAINLOOP(Ab, Bb, sbase, acc)                                       \
    {                                                                           \
        _Pragma("unroll")                                                       \
        for (int s = 0; s < STAGES - 1; s++) {                                  \
            const uint32_t stA = sbase + s * STAGE_BYTES;                       \
            const uint32_t stB = stA + 16384u;                                  \
            const int kb = s * BK;                                              \
            _Pragma("unroll")                                                   \
            for (int t = 0; t < 4; t++) {                                       \
                const int c = tid + t * 256;                                    \
                const int r = c >> 3, u = c & 7;                                \
                cp16(stA + SWZ((uint32_t)(r * 128 + u * 16)), Ab + (size_t)r * D_MOD + kb + u * 8); \
                cp16(stB + SWZ((uint32_t)(r * 128 + u * 16)), Bb + (size_t)r * D_MOD + kb + u * 8); \
            }                                                                   \
            asm volatile("cp.async.commit_group;" ::: "memory");                \
        }                                                                       \
        const int lrow = lane & 15;                                             \
        const int lcol = (lane >> 4) * 16;                                      \
        int sc = 0, sl = STAGES - 1;                                            \
        for (int i = 0; i < NSLAB; i++) {                                       \
            asm volatile("cp.async.wait_group %0;" :: "n"(STAGES - 2) : "memory"); \
            __syncthreads();                                                    \
            if (i + STAGES - 1 < NSLAB) {                                       \
                const uint32_t stA = sbase + sl * STAGE_BYTES;                  \
                const uint32_t stB = stA + 16384u;                              \
                const int kb = (i + STAGES - 1) * BK;                           \
                _Pragma("unroll")                                               \
                for (int t = 0; t < 4; t++) {                                   \
                    const int c = tid + t * 256;                                \
                    const int r = c >> 3, u = c & 7;                            \
                    cp16(stA + SWZ((uint32_t)(r * 128 + u * 16)), Ab + (size_t)r * D_MOD + kb + u * 8); \
                    cp16(stB + SWZ((uint32_t)(r * 128 + u * 16)), Bb + (size_t)r * D_MOD + kb + u * 8); \
                }                                                               \
            }                                                                   \
            asm volatile("cp.async.commit_group;" ::: "memory");                \
            sl = (sl + 1 == STAGES) ? 0 : sl + 1;                               \
            const uint32_t stA = sbase + sc * STAGE_BYTES;                      \
            const uint32_t stB = stA + 16384u;                                  \
            sc = (sc + 1 == STAGES) ? 0 : sc + 1;                               \
            _Pragma("unroll")                                                   \
            for (int ks = 0; ks < BK / 16; ks++) {                              \
                uint32_t afr[4][4], bfr[2][4];                                  \
                _Pragma("unroll")                                               \
                for (int mt = 0; mt < 4; mt++)                                  \
                    ldmx4(afr[mt], stA + SWZ((uint32_t)((wm * 64 + mt * 16 + lrow) * 128 + ks * 32 + lcol))); \
                _Pragma("unroll")                                               \
                for (int bt = 0; bt < 2; bt++)                                  \
                    ldmx4(bfr[bt], stB + SWZ((uint32_t)((wn * 32 + bt * 16 + lrow) * 128 + ks * 32 + lcol))); \
                _Pragma("unroll")                                               \
                for (int mt = 0; mt < 4; mt++)                                  \
                    _Pragma("unroll")                                           \
                    for (int nt = 0; nt < 4; nt++) {                            \
                        const int bt = nt >> 1, sub = nt & 1;                   \
                        mma16816(acc[mt][nt], afr[mt], bfr[bt][sub], bfr[bt][sub + 2]); \
                    }                                                           \
            }                                                                   \
        }                                                                       \
    }

// ---------------------------------------------------------------------------
// Fused QKV projection GEMM. grid = (48, 32). bn segment: 0-15 Q, 16-31 K, 32-47 V.
// Q -> g_qh fp16 (scaled by 0.125*log2e for exp2-domain softmax).
// K/V -> cache f32 (remapped) + fp16 copies.
// ---------------------------------------------------------------------------
__global__ __launch_bounds__(256, 2)
void gemm_qkv_kernel(const __half* __restrict__ A, const __half* __restrict__ B,
                     const float* __restrict__ bq, const float* __restrict__ bk,
                     const float* __restrict__ bv, float* __restrict__ cache,
                     __half* __restrict__ qh, __half* __restrict__ kh,
                     __half* __restrict__ vh)
{
    extern __shared__ char dsmem_raw[];
    __shared__ float bias_s[128];

    const int tid  = threadIdx.x;
    const int lane = tid & 31;
    const int wid  = tid >> 5;
    const int wm   = wid & 1;
    const int wn   = wid >> 1;
    const int bm = blockIdx.y, bn = blockIdx.x;
    const int seg = bn >> 4;           // 0=q 1=k 2=v
    const int bnn = bn & 15;

    uint32_t sbase = smem_u32(dsmem_raw);
    sbase = (sbase + 1023u) & ~1023u;

    const float* bp = seg == 0 ? bq : seg == 1 ? bk : bv;
    if (tid < 128) bias_s[tid] = bp[bnn * 128 + tid];

    const __half* Ab = A + (size_t)bm * 128 * D_MOD;
    const __half* Bb = B + (size_t)bn * 128 * D_MOD;

    float acc[4][4][4];
    #pragma unroll
    for (int i = 0; i < 4; i++)
        #pragma unroll
        for (int j = 0; j < 4; j++)
            #pragma unroll
            for (int q = 0; q < 4; q++) acc[i][j][q] = 0.0f;

    GEMM_MAINLOOP(Ab, Bb, sbase, acc)

    __half* hout = seg == 0 ? qh : seg == 1 ? kh : vh;
    // Q scale: HD^-0.5 * log2(e) so attention softmax runs in exp2 domain
    const float hscale = seg == 0 ? 0.18033688f : 1.0f;

    const int g = lane >> 2, t2 = (lane & 3) * 2;
    #pragma unroll
    for (int mt = 0; mt < 4; mt++) {
        #pragma unroll
        for (int hm = 0; hm < 2; hm++) {
            const int row_g = bm * 128 + wm * 64 + mt * 16 + hm * 8 + g;
            __half* Hrow = hout + (size_t)row_g * D_MOD + bnn * 128;
            float* Crow = nullptr;
            if (seg) {
                const int bb = row_g >> 10, tt = row_g & 1023;
                Crow = cache + (long long)bb * 2 * TNLL + (seg == 2 ? TNLL : 0)
                             + (long long)tt * D_MOD + bnn * 128;
            }
            #pragma unroll
            for (int nt = 0; nt < 4; nt++) {
                const int col = wn * 32 + nt * 8 + t2;
                float2 v;
                v.x = acc[mt][nt][hm * 2 + 0] + bias_s[col];
                v.y = acc[mt][nt][hm * 2 + 1] + bias_s[col + 1];
                *(__half2*)(Hrow + col) = __floats2half2_rn(v.x * hscale, v.y * hscale);
                if (seg) *(float2*)(Crow + col) = v;
            }
        }
    }
}

// ---------------------------------------------------------------------------
// Output projection GEMM: out(f32) = ctxh @ WoT^T + bo. grid = (16, 32).
// ---------------------------------------------------------------------------
__global__ __launch_bounds__(256, 2)
void gemm_out_kernel(const __half* __restrict__ A, const __half* __restrict__ B,
                     const float* __restrict__ bias, float* __restrict__ C)
{
    extern __shared__ char dsmem_raw[];
    __shared__ float bias_s[128];

    const int tid  = threadIdx.x;
    const int lane = tid & 31;
    const int wid  = tid >> 5;
    const int wm   = wid & 1;
    const int wn   = wid >> 1;
    const int bm = blockIdx.y, bn = blockIdx.x;

    uint32_t sbase = smem_u32(dsmem_raw);
    sbase = (sbase + 1023u) & ~1023u;

    if (tid < 128) bias_s[tid] = bias[bn * 128 + tid];

    const __half* Ab = A + (size_t)bm * 128 * D_MOD;
    const __half* Bb = B + (size_t)bn * 128 * D_MOD;

    float acc[4][4][4];
    #pragma unroll
    for (int i = 0; i < 4; i++)
        #pragma unroll
        for (int j = 0; j < 4; j++)
            #pragma unroll
            for (int q = 0; q < 4; q++) acc[i][j][q] = 0.0f;

    GEMM_MAINLOOP(Ab, Bb, sbase, acc)

    const int g = lane >> 2, t2 = (lane & 3) * 2;
    #pragma unroll
    for (int mt = 0; mt < 4; mt++) {
        #pragma unroll
        for (int hm = 0; hm < 2; hm++) {
            const int row_g = bm * 128 + wm * 64 + mt * 16 + hm * 8 + g;
            float* Crow = C + (size_t)row_g * D_MOD + bn * 128;
            #pragma unroll
            for (int nt = 0; nt < 4; nt++) {
                const int col = wn * 32 + nt * 8 + t2;
                float2 v;
                v.x = acc[mt][nt][hm * 2 + 0] + bias_s[col];
                v.y = acc[mt][nt][hm * 2 + 1] + bias_s[col + 1];
                *(float2*)(Crow + col) = v;
            }
        }
    }
}

// ---------------------------------------------------------------------------
// HMMA flash attention (causal, exp2 domain). CTA = 128 queries of one (b,h).
// 256 thr / 8 warps, warp owns 16 q-rows. Softmax exponentials computed as
// fp16x2 ex2; the exp results ARE the PV A-fragments.
// smem: Q 16KB + 2 stages x (K 16KB + V 16KB) = 80KB.
// ---------------------------------------------------------------------------
__global__ __launch_bounds__(256, 1)
void attn_hmma_kernel(const __half* __restrict__ qh, const __half* __restrict__ kh,
                      const __half* __restrict__ vh, __half* __restrict__ ctxh)
{
    extern __shared__ char dsmem_raw[];
    uint32_t sbase = smem_u32(dsmem_raw);
    sbase = (sbase + 1023u) & ~1023u;
    const uint32_t Qsm = sbase;

    const int qt = (int)(gridDim.x - 1 - blockIdx.x);   // reversed: heavy CTAs first
    const int h  = blockIdx.y;
    const int b  = blockIdx.z;
    const int tid = threadIdx.x;
    const int lane = tid & 31;
    const int wid  = tid >> 5;
    const int m0   = wid * 16;

    const size_t bh_off = ((size_t)b * T_SEQ) * D_MOD + h * HDIM;
    const __half* Qg = qh + bh_off + (size_t)qt * 128 * D_MOD;
    const __half* Kg = kh + bh_off;
    const __half* Vg = vh + bh_off;

    // prologue: Q + (K,V) tile 0 in one group
    #pragma unroll
    for (int t = 0; t < 4; t++) {
        const int c = tid + t * 256;
        const int r = c >> 3, u = c & 7;
        cp16(Qsm + SWZ((uint32_t)(r * 128 + u * 16)), Qg + (size_t)r * D_MOD + u * 8);
    }
    {
        const uint32_t Kst = sbase + 16384u, Vst = Kst + 16384u;
        #pragma unroll
        for (int t = 0; t < 4; t++) {
            const int c = tid + t * 256;
            const int r = c >> 3, u = c & 7;
            cp16(Kst + SWZ((uint32_t)(r * 128 + u * 16)), Kg + (size_t)r * D_MOD + u * 8);
            cp16(Vst + SWZ((uint32_t)(r * 128 + u * 16)), Vg + (size_t)r * D_MOD + u * 8);
        }
        asm volatile("cp.async.commit_group;" ::: "memory");
    }

    const int lrow = lane & 15;
    const int lcol = (lane >> 4) * 16;

    uint32_t qf[4][4];
    float oacc[8][4];
    #pragma unroll
    for (int j = 0; j < 8; j++)
        #pragma unroll
        for (int q = 0; q < 4; q++) oacc[j][q] = 0.0f;
    float mrun0 = -1e30f, mrun1 = -1e30f, lrun0 = 0.0f, lrun1 = 0.0f;

    for (int i = 0; i <= qt; i++) {
        const int s = i & 1;
        if (i + 1 <= qt) {
            const uint32_t Kst = sbase + 16384u + (uint32_t)(s ^ 1) * 32768u;
            const uint32_t Vst = Kst + 16384u;
            const __half* Kn = Kg + (size_t)(i + 1) * 128 * D_MOD;
            const __half* Vn = Vg + (size_t)(i + 1) * 128 * D_MOD;
            #pragma unroll
            for (int t = 0; t < 4; t++) {
                const int c = tid + t * 256;
                const int r = c >> 3, u = c & 7;
                cp16(Kst + SWZ((uint32_t)(r * 128 + u * 16)), Kn + (size_t)r * D_MOD + u * 8);
                cp16(Vst + SWZ((uint32_t)(r * 128 + u * 16)), Vn + (size_t)r * D_MOD + u * 8);
            }
            asm volatile("cp.async.commit_group;" ::: "memory");
            asm volatile("cp.async.wait_group 1;" ::: "memory");
        } else {
            asm volatile("cp.async.wait_group 0;" ::: "memory");
        }
        __syncthreads();   // also orders: prior-iter compute done before these loads land

        if (i == 0) {
            #pragma unroll
            for (int ks = 0; ks < 4; ks++)
                ldmx4(qf[ks], Qsm + SWZ((uint32_t)((m0 + lrow) * 128 + ks * 32 + lcol)));
        }

        const uint32_t Kst = sbase + 16384u + (uint32_t)s * 32768u;
        const uint32_t Vst = Kst + 16384u;

        // S = Q @ K^T : 16 q-rows x 128 keys per warp (exp2-domain logits)
        float sacc[16][4];
        #pragma unroll
        for (int nt = 0; nt < 16; nt++)
            #pragma unroll
            for (int q = 0; q < 4; q++) sacc[nt][q] = 0.0f;

        #pragma unroll
        for (int gblk = 0; gblk < 8; gblk++) {       // 16 keys per block
            #pragma unroll
            for (int ks = 0; ks < 4; ks++) {
                uint32_t kf[4];
                ldmx4(kf, Kst + SWZ((uint32_t)((gblk * 16 + lrow) * 128 + ks * 32 + lcol)));
                mma16816(sacc[gblk * 2 + 0], qf[ks], kf[0], kf[2]);
                mma16816(sacc[gblk * 2 + 1], qf[ks], kf[1], kf[3]);
            }
        }

        // causal mask on diagonal tile
        if (i == qt) {
            const int row0 = m0 + (lane >> 2);
            #pragma unroll
            for (int nt = 0; nt < 16; nt++) {
                const int cb = nt * 8 + (lane & 3) * 2;
                if (cb + 0 > row0) sacc[nt][0] = -1e30f;
                if (cb + 1 > row0) sacc[nt][1] = -1e30f;
                if (cb + 0 > row0 + 8) sacc[nt][2] = -1e30f;
                if (cb + 1 > row0 + 8) sacc[nt][3] = -1e30f;
            }
        }

        // online softmax (rows r = lane>>2 and r+8); P = exp2(s - mnew) in fp16x2
        float mx0 = -1e30f, mx1 = -1e30f;
        #pragma unroll
        for (int nt = 0; nt < 16; nt++) {
            mx0 = fmaxf(mx0, fmaxf(sacc[nt][0], sacc[nt][1]));
            mx1 = fmaxf(mx1, fmaxf(sacc[nt][2], sacc[nt][3]));
        }
        mx0 = fmaxf(mx0, __shfl_xor_sync(0xffffffffu, mx0, 1));
        mx0 = fmaxf(mx0, __shfl_xor_sync(0xffffffffu, mx0, 2));
        mx1 = fmaxf(mx1, __shfl_xor_sync(0xffffffffu, mx1, 1));
        mx1 = fmaxf(mx1, __shfl_xor_sync(0xffffffffu, mx1, 2));

        const float mnew0 = fmaxf(mrun0, mx0);
        const float mnew1 = fmaxf(mrun1, mx1);
        const float alpha0 = exp2f(mrun0 - mnew0);
        const float alpha1 = exp2f(mrun1 - mnew1);

        uint32_t pf0[16], pf1[16];   // fp16x2 P: rows r / r+8, cols nt*8+{t2,t2+1}
        float sum0 = 0.0f, sum1 = 0.0f;
        #pragma unroll
        for (int nt = 0; nt < 16; nt++) {
            __half2 d0 = __floats2half2_rn(sacc[nt][0] - mnew0, sacc[nt][1] - mnew0);
            __half2 d1 = __floats2half2_rn(sacc[nt][2] - mnew1, sacc[nt][3] - mnew1);
            pf0[nt] = ex2_f16x2(*(uint32_t*)&d0);
            pf1[nt] = ex2_f16x2(*(uint32_t*)&d1);
            const float2 e0 = __half22float2(*(__half2*)&pf0[nt]);
            const float2 e1 = __half22float2(*(__half2*)&pf1[nt]);
            sum0 += e0.x + e0.y;
            sum1 += e1.x + e1.y;
        }
        sum0 += __shfl_xor_sync(0xffffffffu, sum0, 1);
        sum0 += __shfl_xor_sync(0xffffffffu, sum0, 2);
        sum1 += __shfl_xor_sync(0xffffffffu, sum1, 1);
        sum1 += __shfl_xor_sync(0xffffffffu, sum1, 2);

        lrun0 = lrun0 * alpha0 + sum0;
        lrun1 = lrun1 * alpha1 + sum1;
        mrun0 = mnew0; mrun1 = mnew1;

        #pragma unroll
        for (int j = 0; j < 8; j++) {
            oacc[j][0] *= alpha0; oacc[j][1] *= alpha0;
            oacc[j][2] *= alpha1; oacc[j][3] *= alpha1;
        }

        // O += P @ V  (P fragments directly from pf arrays)
        #pragma unroll
        for (int ksv = 0; ksv < 8; ksv++) {          // 16 keys per step
            uint32_t paf[4];
            paf[0] = pf0[2 * ksv];
            paf[1] = pf1[2 * ksv];
            paf[2] = pf0[2 * ksv + 1];
            paf[3] = pf1[2 * ksv + 1];
            #pragma unroll
            for (int j = 0; j < 4; j++) {            // 16 hd cols per trans load
                uint32_t vf[4];
                ldmx4t(vf, Vst + SWZ((uint32_t)((ksv * 16 + lrow) * 128 + j * 32 + lcol)));
                mma16816(oacc[2 * j + 0], paf, vf[0], vf[1]);
                mma16816(oacc[2 * j + 1], paf, vf[2], vf[3]);
            }
        }
        // no trailing sync: next iteration's top barrier orders smem reuse
    }

    // epilogue: normalize, write ctx fp16 (merged layout)
    const float inv0 = 1.0f / lrun0;
    const float inv1 = 1.0f / lrun1;
    const int r0 = qt * 128 + m0 + (lane >> 2);
    __half* C0 = ctxh + ((size_t)b * T_SEQ + r0) * D_MOD + h * HDIM + (lane & 3) * 2;
    __half* C1 = C0 + 8ull * D_MOD;
    #pragma unroll
    for (int j = 0; j < 8; j++) {
        *(__half2*)(C0 + j * 8) = __floats2half2_rn(oacc[j][0] * inv0, oacc[j][1] * inv0);
        *(__half2*)(C1 + j * 8) = __floats2half2_rn(oacc[j][2] * inv1, oacc[j][3] * inv1);
    }
}

// ---------------------------------------------------------------------------
// Launch
// ---------------------------------------------------------------------------
extern "C" void kernel_launch(void* const* d_in, const int* in_sizes, int n_in,
                              void* d_out, int out_size)
{
    const float* x  = (const float*)d_in[0];
    const float* Wq = (const float*)d_in[4];
    const float* bq = (const float*)d_in[5];
    const float* Wk = (const float*)d_in[6];
    const float* bk = (const float*)d_in[7];
    const float* Wv = (const float*)d_in[8];
    const float* bv = (const float*)d_in[9];
    const float* Wo = (const float*)d_in[10];
    const float* bo = (const float*)d_in[11];

    float* out = (float*)d_out;
    float* cache_out = out + (size_t)M_ROWS * D_MOD;

    __half *xh, *wh, *qh, *kh, *vh, *ctxh;
    cudaGetSymbolAddress((void**)&xh, g_xh);
    cudaGetSymbolAddress((void**)&wh, g_wh);
    cudaGetSymbolAddress((void**)&qh, g_qh);
    cudaGetSymbolAddress((void**)&kh, g_kh);
    cudaGetSymbolAddress((void**)&vh, g_vh);
    cudaGetSymbolAddress((void**)&ctxh, g_ctxh);

    const int smem_gemm = STAGES * STAGE_BYTES + 1024;          // 99 KB
    const int smem_attn = 16384 + 2 * 32768 + 1024;             // 82 KB
    cudaFuncSetAttribute(gemm_qkv_kernel, cudaFuncAttributeMaxDynamicSharedMemorySize, smem_gemm);
    cudaFuncSetAttribute(gemm_out_kernel, cudaFuncAttributeMaxDynamicSharedMemorySize, smem_gemm);
    cudaFuncSetAttribute(attn_hmma_kernel, cudaFuncAttributeMaxDynamicSharedMemorySize, smem_attn);

    const size_t WSZ = (size_t)D_MOD * D_MOD;

    // 1) prep
    convert_x_kernel<<<(M_ROWS * D_MOD) / (256 * 4), 256>>>(x, xh);
    dim3 tgrid(D_MOD / 32, D_MOD / 32, 4);
    convert_wt_kernel<<<tgrid, 256>>>(Wq, Wk, Wv, Wo, wh);

    // 2) fused QKV projection
    dim3 qkvgrid(48, 32);
    gemm_qkv_kernel<<<qkvgrid, 256, smem_gemm>>>(xh, wh, bq, bk, bv,
                                                 cache_out, qh, kh, vh);

    // 3) HMMA causal flash attention
    dim3 agrid(T_SEQ / 128, NHEAD, BATCH);   // (8, 32, 4)
    attn_hmma_kernel<<<agrid, 256, smem_attn>>>(qh, kh, vh, ctxh);

    // 4) output projection
    dim3 ogrid(16, 32);
    gemm_out_kernel<<<ogrid, 256, smem_gemm>>>(ctxh, wh + 3 * WSZ, bo, out);
}